// round 12
// baseline (speedup 1.0000x reference)
#include <cuda_runtime.h>
#include <cuda_bf16.h>
#include <math.h>
#include <stdint.h>

// ---------------- problem constants ----------------
#define BATCH    2
#define SEQ      1024
#define DMODEL   1024
#define DINNER   2048
#define DSTATE   16
#define NTOK     (BATCH * SEQ)          // 2048
#define XW       (DINNER + 2 * DSTATE)  // 2080
#define NSEG     32
#define GSEG     32

// ---------------- fp32 scratch ----------------
__device__ float g_xr [NTOK * 2 * DINNER];
__device__ float g_xs [NTOK * DINNER];
__device__ float g_ssm[NTOK * XW];      // only B/C cols (2048..2079) used
__device__ float g_dt [NTOK * DINNER];
__device__ float g_P  [BATCH * NSEG * DSTATE * DINNER];
__device__ float g_Q  [BATCH * NSEG * DSTATE * DINNER];
__device__ float g_H  [BATCH * NSEG * DSTATE * DINNER];

// ---------------- bf16 split buffers ----------------
__device__ __nv_bfloat16 g_ah0[NTOK * DINNER], g_al0[NTOK * DINNER];
__device__ __nv_bfloat16 g_ah1[NTOK * DINNER], g_al1[NTOK * DINNER];
__device__ __nv_bfloat16 g_w1h[4096 * 1024], g_w1l[4096 * 1024];   // W_in^T
__device__ __nv_bfloat16 g_w2h[2176 * 2048], g_w2l[2176 * 2048];   // [Wc | W_x_BC]^T
__device__ __nv_bfloat16 g_w3h[2048 * 2048], g_w3l[2048 * 2048];   // W_dt^T
__device__ __nv_bfloat16 g_w4h[1024 * 2048], g_w4l[1024 * 2048];   // W_out^T
__device__ __nv_bfloat16 g_wxd_h[2048 * 2048], g_wxd_l[2048 * 2048]; // W_x[:, :2048] direct

// ---------------- helpers ----------------
__device__ __forceinline__ uint32_t smem_u32(const void* p) {
    uint32_t a;
    asm("{ .reg .u64 t; cvta.to.shared.u64 t, %1; cvt.u32.u64 %0, t; }"
        : "=r"(a) : "l"(p));
    return a;
}
__device__ __forceinline__ void cp_async16s(uint32_t saddr, const void* gptr) {
    asm volatile("cp.async.cg.shared.global [%0], [%1], 16;\n"
                 :: "r"(saddr), "l"(gptr));
}
__device__ __forceinline__ void cp_commit() {
    asm volatile("cp.async.commit_group;\n");
}
__device__ __forceinline__ void ldsm4(uint32_t* r, uint32_t a) {
    asm volatile("ldmatrix.sync.aligned.m8n8.x4.shared.b16 {%0,%1,%2,%3}, [%4];"
                 : "=r"(r[0]), "=r"(r[1]), "=r"(r[2]), "=r"(r[3]) : "r"(a));
}
__device__ __forceinline__ void mma16816(float* c, const uint32_t* a,
                                         const uint32_t* b) {
    asm volatile(
        "mma.sync.aligned.m16n8k16.row.col.f32.bf16.bf16.f32 "
        "{%0,%1,%2,%3}, {%4,%5,%6,%7}, {%8,%9}, {%0,%1,%2,%3};"
        : "+f"(c[0]), "+f"(c[1]), "+f"(c[2]), "+f"(c[3])
        : "r"(a[0]), "r"(a[1]), "r"(a[2]), "r"(a[3]), "r"(b[0]), "r"(b[1]));
}
__device__ __forceinline__ void split2(__nv_bfloat16* h, __nv_bfloat16* l,
                                       float v0, float v1) {
    const __nv_bfloat16 h0 = __float2bfloat16(v0);
    const __nv_bfloat16 h1 = __float2bfloat16(v1);
    __nv_bfloat162 hh; hh.x = h0; hh.y = h1;
    __nv_bfloat162 ll;
    ll.x = __float2bfloat16(v0 - __bfloat162float(h0));
    ll.y = __float2bfloat16(v1 - __bfloat162float(h1));
    *reinterpret_cast<__nv_bfloat162*>(h) = hh;
    *reinterpret_cast<__nv_bfloat162*>(l) = ll;
}
__device__ __forceinline__ float fast_silu(float a) {
    return __fdividef(a, 1.f + __expf(-a));
}

// ---------------- RMSNorm, split output ----------------
__global__ void rmsnorm_split_kernel(const float* __restrict__ x,
                                     const float* __restrict__ w,
                                     __nv_bfloat16* __restrict__ oh,
                                     __nv_bfloat16* __restrict__ ol) {
    const int t   = blockIdx.x;
    const int tid = threadIdx.x;
    const float4 v = reinterpret_cast<const float4*>(x + t * DMODEL)[tid];
    float s = v.x * v.x + v.y * v.y + v.z * v.z + v.w * v.w;
    #pragma unroll
    for (int o = 16; o; o >>= 1) s += __shfl_xor_sync(0xffffffffu, s, o);
    __shared__ float red[8];
    __shared__ float sscale;
    if ((tid & 31) == 0) red[tid >> 5] = s;
    __syncthreads();
    if (tid == 0) {
        float tot = 0.f;
        #pragma unroll
        for (int i = 0; i < 8; ++i) tot += red[i];
        sscale = rsqrtf(tot * (1.0f / DMODEL) + 1e-5f);
    }
    __syncthreads();
    const float sc = sscale;
    const float4 wv = reinterpret_cast<const float4*>(w)[tid];
    const int base = t * DMODEL + tid * 4;
    split2(&oh[base],     &ol[base],     v.x * sc * wv.x, v.y * sc * wv.y);
    split2(&oh[base + 2], &ol[base + 2], v.z * sc * wv.z, v.w * sc * wv.w);
}

// ---------------- depthwise causal conv + SiLU (float4/thread) ----------------
__global__ void conv_silu_kernel(const float* __restrict__ xr,
                                 const float* __restrict__ cw,
                                 const float* __restrict__ cb,
                                 float* __restrict__ xs,
                                 __nv_bfloat16* __restrict__ oh,
                                 __nv_bfloat16* __restrict__ ol) {
    const int idx = (blockIdx.x * blockDim.x + threadIdx.x) * 4;
    const int d   = idx & (DINNER - 1);
    const int tok = idx >> 11;
    const int l   = tok & (SEQ - 1);
    const float4* cw4 = reinterpret_cast<const float4*>(cw);
    const float4 w0 = cw4[d];
    const float4 w1 = cw4[d + 1];
    const float4 w2 = cw4[d + 2];
    const float4 w3 = cw4[d + 3];
    float4 a = reinterpret_cast<const float4*>(cb)[d >> 2];
    #pragma unroll
    for (int j = 0; j < 4; ++j) {
        const int ls = l - 3 + j;
        if (ls >= 0) {
            const float4 xv = *reinterpret_cast<const float4*>(
                &xr[(tok + j - 3) * (2 * DINNER) + d]);
            const float t0 = (j == 0) ? w0.x : (j == 1) ? w0.y : (j == 2) ? w0.z : w0.w;
            const float t1 = (j == 0) ? w1.x : (j == 1) ? w1.y : (j == 2) ? w1.z : w1.w;
            const float t2 = (j == 0) ? w2.x : (j == 1) ? w2.y : (j == 2) ? w2.z : w2.w;
            const float t3 = (j == 0) ? w3.x : (j == 1) ? w3.y : (j == 2) ? w3.z : w3.w;
            a.x = fmaf(t0, xv.x, a.x);
            a.y = fmaf(t1, xv.y, a.y);
            a.z = fmaf(t2, xv.z, a.z);
            a.w = fmaf(t3, xv.w, a.w);
        }
    }
    a.x = fast_silu(a.x);  a.y = fast_silu(a.y);
    a.z = fast_silu(a.z);  a.w = fast_silu(a.w);
    *reinterpret_cast<float4*>(&xs[idx]) = a;
    split2(&oh[idx],     &ol[idx],     a.x, a.y);
    split2(&oh[idx + 2], &ol[idx + 2], a.z, a.w);
}

// ---------------- merged weight split (5 segments) ----------------
__global__ void wsplit_all_kernel(const float* __restrict__ W1,
                                  const float* __restrict__ W2,
                                  const float* __restrict__ W3,
                                  const float* __restrict__ W4,
                                  __nv_bfloat16* __restrict__ w1h, __nv_bfloat16* __restrict__ w1l,
                                  __nv_bfloat16* __restrict__ w2h, __nv_bfloat16* __restrict__ w2l,
                                  __nv_bfloat16* __restrict__ w3h, __nv_bfloat16* __restrict__ w3l,
                                  __nv_bfloat16* __restrict__ w4h, __nv_bfloat16* __restrict__ w4l,
                                  __nv_bfloat16* __restrict__ wdh, __nv_bfloat16* __restrict__ wdl) {
    const int id = blockIdx.x;
    const int tx = threadIdx.x, ty = threadIdx.y;   // 32 x 8

    if (id >= 10496) {   // direct split of W_x[:, :2048]
        const int rel = id - 10496;
        const int j0 = (rel & 63) * 32, k0 = (rel >> 6) * 32;
        #pragma unroll
        for (int r = 0; r < 4; ++r) {
            const int k = k0 + ty + 8 * r, j = j0 + tx;
            const float v = W2[(size_t)k * XW + j];
            const __nv_bfloat16 hi = __float2bfloat16(v);
            wdh[(size_t)k * 2048 + j] = hi;
            wdl[(size_t)k * 2048 + j] = __float2bfloat16(v - __bfloat162float(hi));
        }
        return;
    }

    const float* W; __nv_bfloat16 *Th, *Tl;
    int K, N, ld, n0, k0;
    if (id < 4096) {
        W = W1; Th = w1h; Tl = w1l; K = 1024; N = 4096; ld = 4096;
        n0 = (id & 127) * 32; k0 = (id >> 7) * 32;
    } else if (id < 4352) {
        const int rel = id - 4096;
        W = W2; Th = w2h; Tl = w2l; K = 2048; N = XW; ld = XW;
        n0 = 2048 + (rel & 3) * 32; k0 = (rel >> 2) * 32;
    } else if (id < 8448) {
        const int rel = id - 4352;
        W = W3; Th = w3h; Tl = w3l; K = 2048; N = 2048; ld = 2048;
        n0 = (rel & 63) * 32; k0 = (rel >> 6) * 32;
    } else {
        const int rel = id - 8448;
        W = W4; Th = w4h; Tl = w4l; K = 2048; N = 1024; ld = 1024;
        n0 = (rel & 31) * 32; k0 = (rel >> 5) * 32;
    }

    __shared__ float tile[32][33];
    #pragma unroll
    for (int r = 0; r < 4; ++r) {
        const int k = k0 + ty + 8 * r, n = n0 + tx;
        tile[ty + 8 * r][tx] = (n < N) ? W[(size_t)k * ld + n] : 0.f;
    }
    __syncthreads();
    #pragma unroll
    for (int r = 0; r < 4; ++r) {
        const int nrow = n0 + ty + 8 * r, k = k0 + tx;
        const float v = tile[tx][ty + 8 * r];
        const __nv_bfloat16 hi = __float2bfloat16(v);
        Th[(size_t)nrow * K + k] = hi;
        Tl[(size_t)nrow * K + k] = __float2bfloat16(v - __bfloat162float(hi));
    }
}

// ---------------- mma.sync bf16-split GEMM (templated BM) ----------------
#define TCK 32

#define ACT_NONE     0
#define ACT_RESADD   2
#define ACT_DTBC     3

template <int ACT, int SPLIT, int BM>
__global__ __launch_bounds__(256, 2)
void tcgemm_kernel(const __nv_bfloat16* __restrict__ Ah,
                   const __nv_bfloat16* __restrict__ Al,
                   const __nv_bfloat16* __restrict__ Bh,
                   const __nv_bfloat16* __restrict__ Bl,
                   float* __restrict__ D, const float* __restrict__ Res,
                   __nv_bfloat16* __restrict__ Sh, __nv_bfloat16* __restrict__ Sl,
                   int N, int K, int ldd, int ldr) {
    constexpr int TM    = BM / 32;
    constexpr int ALOFF = BM * 64;
    constexpr int BOFF  = 2 * BM * 64;
    constexpr int STAGE = BM * 128 + 16384;

    extern __shared__ unsigned char sm[];
    const uint32_t smb = smem_u32(sm);

    const int tid  = threadIdx.x;
    const int lane = tid & 31;
    const int wid  = tid >> 5;
    const int wm   = wid >> 2;
    const int wn   = wid & 3;
    const int m0   = blockIdx.y * BM;
    const int n0   = blockIdx.x * 128;

    const int lrowB = tid >> 1;
    const int gpB   = (tid & 1) * 2;
    const int swB   = (lrowB >> 1) & 3;
    const uint32_t dstB0 = BOFF + lrowB * 64 + (((gpB + 0) ^ swB) << 4);
    const uint32_t dstB1 = BOFF + lrowB * 64 + (((gpB + 1) ^ swB) << 4);
    const __nv_bfloat16* srcBh = Bh + (size_t)(n0 + lrowB) * K + gpB * 8;
    const __nv_bfloat16* srcBl = Bl + (size_t)(n0 + lrowB) * K + gpB * 8;

    uint32_t dstA0, dstA1 = 0;
    const __nv_bfloat16 *srcAh, *srcAl;
    if constexpr (BM == 128) {
        dstA0 = lrowB * 64 + (((gpB + 0) ^ swB) << 4);
        dstA1 = lrowB * 64 + (((gpB + 1) ^ swB) << 4);
        srcAh = Ah + (size_t)(m0 + lrowB) * K + gpB * 8;
        srcAl = Al + (size_t)(m0 + lrowB) * K + gpB * 8;
    } else {
        const int lrowA = tid >> 2;
        const int gpA   = tid & 3;
        dstA0 = lrowA * 64 + ((gpA ^ ((lrowA >> 1) & 3)) << 4);
        srcAh = Ah + (size_t)(m0 + lrowA) * K + gpA * 8;
        srcAl = Al + (size_t)(m0 + lrowA) * K + gpA * 8;
    }

    const int agsel = lane >> 4;
    const int rowA  = wm * (BM / 2) + (lane & 15);
    const uint32_t offA = rowA * 64 + ((agsel ^ ((rowA >> 1) & 3)) << 4);
    const int nr    = (lane & 7) + ((lane >> 4) << 3);
    const int kgsel = (lane >> 3) & 1;
    const int rowB  = wn * 32 + nr;
    const uint32_t offB = BOFF + rowB * 64 + ((kgsel ^ ((rowB >> 1) & 3)) << 4);

    const int T = K / TCK;

    auto load_chunk = [&](int stage, int k0) {
        const uint32_t sb_ = smb + stage * STAGE;
        if constexpr (BM == 128) {
            cp_async16s(sb_ + dstA0,         srcAh + k0);
            cp_async16s(sb_ + dstA1,         srcAh + k0 + 8);
            cp_async16s(sb_ + ALOFF + dstA0, srcAl + k0);
            cp_async16s(sb_ + ALOFF + dstA1, srcAl + k0 + 8);
        } else {
            cp_async16s(sb_ + dstA0,         srcAh + k0);
            cp_async16s(sb_ + ALOFF + dstA0, srcAl + k0);
        }
        cp_async16s(sb_ + dstB0,        srcBh + k0);
        cp_async16s(sb_ + dstB1,        srcBh + k0 + 8);
        cp_async16s(sb_ + 8192 + dstB0, srcBl + k0);
        cp_async16s(sb_ + 8192 + dstB1, srcBl + k0 + 8);
        cp_commit();
    };

    load_chunk(0, 0);
    load_chunk(1, TCK);

    float acc[TM][4][4];
    #pragma unroll
    for (int t = 0; t < TM; ++t)
        #pragma unroll
        for (int j = 0; j < 4; ++j)
            #pragma unroll
            for (int q = 0; q < 4; ++q) acc[t][j][q] = 0.f;

    for (int i = 0; i < T; ++i) {
        asm volatile("cp.async.wait_group 1;\n" ::: "memory");
        __syncthreads();

        if (i + 2 < T) load_chunk((i + 2) % 3, (i + 2) * TCK);
        else           cp_commit();

        const uint32_t sb = smb + (i % 3) * STAGE;
        #pragma unroll
        for (int ks = 0; ks < 2; ++ks) {
            const uint32_t kx = ks * 32;
            uint32_t ah_[TM][4], al_[TM][4];
            #pragma unroll
            for (int t = 0; t < TM; ++t) {
                const uint32_t oa = (offA + t * 1024) ^ kx;
                ldsm4(ah_[t], sb + oa);
                ldsm4(al_[t], sb + ALOFF + oa);
            }
            #pragma unroll
            for (int p = 0; p < 2; ++p) {
                uint32_t bh_[4], bl_[4];
                const uint32_t ob = (offB + p * 1024) ^ kx;
                ldsm4(bh_, sb + ob);
                ldsm4(bl_, sb + ob + 8192);
                #pragma unroll
                for (int t = 0; t < TM; ++t) {
                    mma16816(acc[t][2 * p],     ah_[t], bh_);
                    mma16816(acc[t][2 * p + 1], ah_[t], bh_ + 2);
                    mma16816(acc[t][2 * p],     al_[t], bh_);
                    mma16816(acc[t][2 * p + 1], al_[t], bh_ + 2);
                    mma16816(acc[t][2 * p],     ah_[t], bl_);
                    mma16816(acc[t][2 * p + 1], ah_[t], bl_ + 2);
                }
            }
        }
    }

    // ---- epilogue
    const int g  = lane >> 2;
    const int tg = lane & 3;
    #pragma unroll
    for (int t = 0; t < TM; ++t) {
        const int row = m0 + wm * (BM / 2) + t * 16 + g;
        #pragma unroll
        for (int j = 0; j < 4; ++j) {
            const int col = n0 + wn * 32 + j * 8 + 2 * tg;
            if (col < N) {
                float c0 = acc[t][j][0], c1 = acc[t][j][1];
                float c2 = acc[t][j][2], c3 = acc[t][j][3];
                if (ACT == ACT_DTBC) {
                    if (col < DINNER) {
                        c0 = fmaxf(c0, 0.f) + __logf(1.f + __expf(-fabsf(c0)));
                        c1 = fmaxf(c1, 0.f) + __logf(1.f + __expf(-fabsf(c1)));
                        c2 = fmaxf(c2, 0.f) + __logf(1.f + __expf(-fabsf(c2)));
                        c3 = fmaxf(c3, 0.f) + __logf(1.f + __expf(-fabsf(c3)));
                        *reinterpret_cast<float2*>(&D[(size_t)row * ldd + col]) =
                            make_float2(c0, c1);
                        *reinterpret_cast<float2*>(&D[(size_t)(row + 8) * ldd + col]) =
                            make_float2(c2, c3);
                    } else {
                        float* bc = const_cast<float*>(Res);
                        *reinterpret_cast<float2*>(&bc[(size_t)row * ldr + col]) =
                            make_float2(c0, c1);
                        *reinterpret_cast<float2*>(&bc[(size_t)(row + 8) * ldr + col]) =
                            make_float2(c2, c3);
                    }
                    continue;
                }
                if (ACT == ACT_RESADD) {
                    const float2 r0 = *reinterpret_cast<const float2*>(
                        &Res[(size_t)row * ldr + col]);
                    const float2 r1 = *reinterpret_cast<const float2*>(
                        &Res[(size_t)(row + 8) * ldr + col]);
                    c0 += r0.x; c1 += r0.y; c2 += r1.x; c3 += r1.y;
                }
                const bool storef = SPLIT ? (col >= DINNER) : true;
                if (storef) {
                    *reinterpret_cast<float2*>(&D[(size_t)row * ldd + col]) =
                        make_float2(c0, c1);
                    *reinterpret_cast<float2*>(&D[(size_t)(row + 8) * ldd + col]) =
                        make_float2(c2, c3);
                }
                if (SPLIT && col < DINNER) {
                    split2(&Sh[(size_t)row * DINNER + col],
                           &Sl[(size_t)row * DINNER + col], c0, c1);
                    split2(&Sh[(size_t)(row + 8) * DINNER + col],
                           &Sl[(size_t)(row + 8) * DINNER + col], c2, c3);
                }
            }
        }
    }
}

// ---------------- chunked parallel selective scan ----------------
__global__ __launch_bounds__(256)
void scan_p1(const float* __restrict__ dt, const float* __restrict__ xs,
             const float* __restrict__ ssm, const float* __restrict__ A_log,
             float* __restrict__ P, float* __restrict__ Q) {
    __shared__ float Bsh[GSEG][DSTATE];
    const int b = blockIdx.z, s = blockIdx.y;
    const int d = blockIdx.x * 256 + threadIdx.x;
    const int tok0 = b * SEQ + s * GSEG;

    for (int v = threadIdx.x; v < GSEG * DSTATE; v += 256) {
        const int l = v >> 4, n = v & 15;
        Bsh[l][n] = ssm[(tok0 + l) * XW + DINNER + n];
    }
    __syncthreads();

    float Ac[DSTATE];
    #pragma unroll
    for (int q = 0; q < 4; ++q) {
        const float4 v = reinterpret_cast<const float4*>(&A_log[d * DSTATE])[q];
        Ac[4 * q + 0] = -__expf(v.x);  Ac[4 * q + 1] = -__expf(v.y);
        Ac[4 * q + 2] = -__expf(v.z);  Ac[4 * q + 3] = -__expf(v.w);
    }

    float h[DSTATE];
    #pragma unroll
    for (int n = 0; n < DSTATE; ++n) h[n] = 0.f;
    float sdt = 0.f;

    for (int l = 0; l < GSEG; ++l) {
        const float dtv = dt[(tok0 + l) * DINNER + d];
        const float xv  = xs[(tok0 + l) * DINNER + d];
        sdt += dtv;
        const float dtx = dtv * xv;
        #pragma unroll
        for (int n = 0; n < DSTATE; ++n)
            h[n] = fmaf(__expf(Ac[n] * dtv), h[n], dtx * Bsh[l][n]);
    }

    const int basei = ((b * NSEG + s) * DSTATE) * DINNER + d;
    #pragma unroll
    for (int n = 0; n < DSTATE; ++n) {
        P[basei + n * DINNER] = __expf(Ac[n] * sdt);
        Q[basei + n * DINNER] = h[n];
    }
}

__global__ void scan_combine(const float* __restrict__ P,
                             const float* __restrict__ Q,
                             float* __restrict__ H) {
    const int t = blockIdx.x * 256 + threadIdx.x;
    const int d = t & (DINNER - 1);
    const int n = (t >> 11) & 15;
    const int b = t >> 15;
    float h = 0.f;
    for (int s = 0; s < NSEG; ++s) {
        const int off = ((b * NSEG + s) * DSTATE + n) * DINNER + d;
        H[off] = h;
        h = fmaf(P[off], h, Q[off]);
    }
}

__global__ __launch_bounds__(256)
void scan_p2(const float* __restrict__ dt, const float* __restrict__ xs,
             const float* __restrict__ ssm, const float* __restrict__ xr,
             const float* __restrict__ A_log, const float* __restrict__ H,
             __nv_bfloat16* __restrict__ yh, __nv_bfloat16* __restrict__ yl) {
    __shared__ float Bsh[GSEG][DSTATE];
    __shared__ float Csh[GSEG][DSTATE];
    const int b = blockIdx.z, s = blockIdx.y;
    const int d = blockIdx.x * 256 + threadIdx.x;
    const int tok0 = b * SEQ + s * GSEG;

    for (int v = threadIdx.x; v < GSEG * DSTATE * 2; v += 256) {
        const int l = v >> 5, j = v & 31;
        const float val = ssm[(tok0 + l) * XW + DINNER + j];
        if (j < DSTATE) Bsh[l][j] = val;
        else            Csh[l][j - DSTATE] = val;
    }
    __syncthreads();

    float Ac[DSTATE];
    #pragma unroll
    for (int q = 0; q < 4; ++q) {
        const float4 v = reinterpret_cast<const float4*>(&A_log[d * DSTATE])[q];
        Ac[4 * q + 0] = -__expf(v.x);  Ac[4 * q + 1] = -__expf(v.y);
        Ac[4 * q + 2] = -__expf(v.z);  Ac[4 * q + 3] = -__expf(v.w);
    }

    const int basei = ((b * NSEG + s) * DSTATE) * DINNER + d;
    float h[DSTATE];
    #pragma unroll
    for (int n = 0; n < DSTATE; ++n) h[n] = H[basei + n * DINNER];

    for (int l = 0; l < GSEG; ++l) {
        const float dtv = dt[(tok0 + l) * DINNER + d];
        const float xv  = xs[(tok0 + l) * DINNER + d];
        const float dtx = dtv * xv;
        float y = 0.f;
        #pragma unroll
        for (int n = 0; n < DSTATE; ++n) {
            h[n] = fmaf(__expf(Ac[n] * dtv), h[n], dtx * Bsh[l][n]);
            y = fmaf(h[n], Csh[l][n], y);
        }
        const float r = xr[(tok0 + l) * (2 * DINNER) + DINNER + d];
        const float v = y * fast_silu(r);
        const __nv_bfloat16 hi = __float2bfloat16(v);
        yh[(tok0 + l) * DINNER + d] = hi;
        yl[(tok0 + l) * DINNER + d] = __float2bfloat16(v - __bfloat162float(hi));
    }
}

// ---------------- launch ----------------
extern "C" void kernel_launch(void* const* d_in, const int* in_sizes, int n_in,
                              void* d_out, int out_size) {
    const float* x      = (const float*)d_in[0];
    const float* rms_w  = (const float*)d_in[1];
    const float* W_in   = (const float*)d_in[2];
    const float* conv_w = (const float*)d_in[3];
    const float* conv_b = (const float*)d_in[4];
    const float* W_x    = (const float*)d_in[5];
    const float* W_dt   = (const float*)d_in[6];
    const float* A_log  = (const float*)d_in[7];
    const float* W_out  = (const float*)d_in[8];
    float* out = (float*)d_out;

    float *xr, *xs, *ssm, *dtb, *P, *Q, *H;
    __nv_bfloat16 *ah0, *al0, *ah1, *al1;
    __nv_bfloat16 *w1h, *w1l, *w2h, *w2l, *w3h, *w3l, *w4h, *w4l, *wdh, *wdl;
    cudaGetSymbolAddress((void**)&xr,  g_xr);
    cudaGetSymbolAddress((void**)&xs,  g_xs);
    cudaGetSymbolAddress((void**)&ssm, g_ssm);
    cudaGetSymbolAddress((void**)&dtb, g_dt);
    cudaGetSymbolAddress((void**)&P,   g_P);
    cudaGetSymbolAddress((void**)&Q,   g_Q);
    cudaGetSymbolAddress((void**)&H,   g_H);
    cudaGetSymbolAddress((void**)&ah0, g_ah0);  cudaGetSymbolAddress((void**)&al0, g_al0);
    cudaGetSymbolAddress((void**)&ah1, g_ah1);  cudaGetSymbolAddress((void**)&al1, g_al1);
    cudaGetSymbolAddress((void**)&w1h, g_w1h);  cudaGetSymbolAddress((void**)&w1l, g_w1l);
    cudaGetSymbolAddress((void**)&w2h, g_w2h);  cudaGetSymbolAddress((void**)&w2l, g_w2l);
    cudaGetSymbolAddress((void**)&w3h, g_w3h);  cudaGetSymbolAddress((void**)&w3l, g_w3l);
    cudaGetSymbolAddress((void**)&w4h, g_w4h);  cudaGetSymbolAddress((void**)&w4l, g_w4l);
    cudaGetSymbolAddress((void**)&wdh, g_wxd_h); cudaGetSymbolAddress((void**)&wdl, g_wxd_l);

    constexpr int SM128 = 3 * (128 * 128 + 16384);   // 98304
    constexpr int SM64  = 3 * (64 * 128 + 16384);    // 73728

    static cudaStream_t s2 = nullptr, s3 = nullptr;
    static cudaEvent_t evW = nullptr, evJoin = nullptr, evA = nullptr, evXr = nullptr;
    if (!s2) {
        cudaFuncSetAttribute(tcgemm_kernel<ACT_NONE, 0, 128>,
            cudaFuncAttributeMaxDynamicSharedMemorySize, SM128);
        cudaFuncSetAttribute(tcgemm_kernel<ACT_NONE, 1, 128>,
            cudaFuncAttributeMaxDynamicSharedMemorySize, SM128);
        cudaFuncSetAttribute(tcgemm_kernel<ACT_DTBC, 0, 128>,
            cudaFuncAttributeMaxDynamicSharedMemorySize, SM128);
        cudaFuncSetAttribute(tcgemm_kernel<ACT_RESADD, 0, 64>,
            cudaFuncAttributeMaxDynamicSharedMemorySize, SM64);
        cudaStreamCreateWithFlags(&s2, cudaStreamNonBlocking);
        cudaStreamCreateWithFlags(&s3, cudaStreamNonBlocking);
        cudaEventCreateWithFlags(&evW,    cudaEventDisableTiming);
        cudaEventCreateWithFlags(&evJoin, cudaEventDisableTiming);
        cudaEventCreateWithFlags(&evA,    cudaEventDisableTiming);
        cudaEventCreateWithFlags(&evXr,   cudaEventDisableTiming);
    }

    // ---- s2: weight split then Wc weight GEMM (both independent of x)
    // s0 first records a fork-root so s2 work is reachable from the capture stream.
    cudaEventRecord(evA, 0);                 // reuse evA as fork-root marker
    cudaStreamWaitEvent(s2, evA, 0);
    wsplit_all_kernel<<<14592, dim3(32, 8), 0, s2>>>(W_in, W_x, W_dt, W_out,
        w1h, w1l, w2h, w2l, w3h, w3l, w4h, w4l, wdh, wdl);
    cudaEventRecord(evW, s2);
    tcgemm_kernel<ACT_NONE, 1, 128><<<dim3(16, 16), 256, SM128, s2>>>(
        w3h, w3l, wdh, wdl, dtb /*scratch, overwritten later*/, nullptr, w2h, w2l,
        2048, 2048, 2048, 0);
    cudaEventRecord(evJoin, s2);

    // ---- s0: rmsnorm concurrent with wsplit
    rmsnorm_split_kernel<<<NTOK, 256>>>(x, rms_w, ah0, al0);

    // GEMM1a: xs half (cols 0..2047) — needs w1 (evW)
    cudaStreamWaitEvent(0, evW, 0);
    tcgemm_kernel<ACT_NONE, 0, 128><<<dim3(16, 16), 256, SM128>>>(
        ah0, al0, w1h, w1l, xr, nullptr, nullptr, nullptr, 2048, 1024, 4096, 0);
    cudaEventRecord(evA, 0);

    // ---- s3: GEMM1b res half (cols 2048..4095), overlaps conv/GEMM2'/scan_p1
    cudaStreamWaitEvent(s3, evA, 0);
    tcgemm_kernel<ACT_NONE, 0, 128><<<dim3(16, 16), 256, SM128, s3>>>(
        ah0, al0, w1h + (size_t)2048 * 1024, w1l + (size_t)2048 * 1024,
        xr + 2048, nullptr, nullptr, nullptr, 2048, 1024, 4096, 0);
    cudaEventRecord(evXr, s3);

    // ---- s0 main chain
    // conv + silu -> xs fp32 + split buf1
    conv_silu_kernel<<<(NTOK * DINNER / 4) / 256, 256>>>(xr, conv_w, conv_b,
                                                         xs, ah1, al1);

    // fused GEMM2': [dt | B | C] = xs @ [Wc | W_x_BC]
    cudaStreamWaitEvent(0, evJoin, 0);
    tcgemm_kernel<ACT_DTBC, 0, 128><<<dim3(17, 16), 256, SM128>>>(
        ah1, al1, w2h, w2l, dtb, ssm, nullptr, nullptr,
        XW, 2048, DINNER, XW);

    // scan (p1/combine need no xr)
    scan_p1<<<dim3(DINNER / 256, NSEG, BATCH), 256>>>(dtb, xs, ssm, A_log, P, Q);
    scan_combine<<<(BATCH * DSTATE * DINNER) / 256, 256>>>(P, Q, H);

    // p2 needs xr res half
    cudaStreamWaitEvent(0, evXr, 0);
    scan_p2<<<dim3(DINNER / 256, NSEG, BATCH), 256>>>(dtb, xs, ssm, xr, A_log, H,
                                                      ah1, al1);

    // out = x + yz @ W_out
    tcgemm_kernel<ACT_RESADD, 0, 64><<<dim3(8, 32), 256, SM64>>>(
        ah1, al1, w4h, w4l, out, x, nullptr, nullptr, 1024, 2048, 1024, 1024);
}

// round 13
// speedup vs baseline: 1.2574x; 1.2574x over previous
#include <cuda_runtime.h>
#include <cuda_bf16.h>
#include <math.h>
#include <stdint.h>

// ---------------- problem constants ----------------
#define BATCH    2
#define SEQ      1024
#define DMODEL   1024
#define DINNER   2048
#define DSTATE   16
#define NTOK     (BATCH * SEQ)          // 2048
#define XW       (DINNER + 2 * DSTATE)  // 2080
#define NSEG     32
#define GSEG     32

// ---------------- fp32 scratch ----------------
__device__ float g_xr [NTOK * 2 * DINNER];
__device__ float g_xs [NTOK * DINNER];
__device__ float g_ssm[NTOK * XW];
__device__ float g_dt [NTOK * DINNER];
__device__ float g_P  [BATCH * NSEG * DSTATE * DINNER];
__device__ float g_Q  [BATCH * NSEG * DSTATE * DINNER];
__device__ float g_H  [BATCH * NSEG * DSTATE * DINNER];

// ---------------- bf16 split buffers ----------------
__device__ __nv_bfloat16 g_ah0[NTOK * DINNER], g_al0[NTOK * DINNER];
__device__ __nv_bfloat16 g_ah1[NTOK * DINNER], g_al1[NTOK * DINNER];
__device__ __nv_bfloat16 g_w1h[4096 * 1024];                        // W_in^T hi only
__device__ __nv_bfloat16 g_w2h[2176 * 2048], g_w2l[2176 * 2048];   // [Wc | W_x_BC]^T hi/lo
__device__ __nv_bfloat16 g_w3h[2048 * 2048], g_w3l[2048 * 2048];   // W_dt^T hi/lo
__device__ __nv_bfloat16 g_w4h[1024 * 2048];                        // W_out^T hi only
__device__ __nv_bfloat16 g_wxd_h[2048 * 2048];                      // W_x[:, :2048] hi only

// ---------------- helpers ----------------
__device__ __forceinline__ uint32_t smem_u32(const void* p) {
    uint32_t a;
    asm("{ .reg .u64 t; cvta.to.shared.u64 t, %1; cvt.u32.u64 %0, t; }"
        : "=r"(a) : "l"(p));
    return a;
}
__device__ __forceinline__ void cp_async16s(uint32_t saddr, const void* gptr) {
    asm volatile("cp.async.cg.shared.global [%0], [%1], 16;\n"
                 :: "r"(saddr), "l"(gptr));
}
__device__ __forceinline__ void cp_commit() {
    asm volatile("cp.async.commit_group;\n");
}
__device__ __forceinline__ void ldsm4(uint32_t* r, uint32_t a) {
    asm volatile("ldmatrix.sync.aligned.m8n8.x4.shared.b16 {%0,%1,%2,%3}, [%4];"
                 : "=r"(r[0]), "=r"(r[1]), "=r"(r[2]), "=r"(r[3]) : "r"(a));
}
__device__ __forceinline__ void mma16816(float* c, const uint32_t* a,
                                         const uint32_t* b) {
    asm volatile(
        "mma.sync.aligned.m16n8k16.row.col.f32.bf16.bf16.f32 "
        "{%0,%1,%2,%3}, {%4,%5,%6,%7}, {%8,%9}, {%0,%1,%2,%3};"
        : "+f"(c[0]), "+f"(c[1]), "+f"(c[2]), "+f"(c[3])
        : "r"(a[0]), "r"(a[1]), "r"(a[2]), "r"(a[3]), "r"(b[0]), "r"(b[1]));
}
__device__ __forceinline__ void split2(__nv_bfloat16* h, __nv_bfloat16* l,
                                       float v0, float v1) {
    const __nv_bfloat16 h0 = __float2bfloat16(v0);
    const __nv_bfloat16 h1 = __float2bfloat16(v1);
    __nv_bfloat162 hh; hh.x = h0; hh.y = h1;
    __nv_bfloat162 ll;
    ll.x = __float2bfloat16(v0 - __bfloat162float(h0));
    ll.y = __float2bfloat16(v1 - __bfloat162float(h1));
    *reinterpret_cast<__nv_bfloat162*>(h) = hh;
    *reinterpret_cast<__nv_bfloat162*>(l) = ll;
}
__device__ __forceinline__ float fast_silu(float a) {
    return __fdividef(a, 1.f + __expf(-a));
}

// ---------------- RMSNorm, split output ----------------
__global__ void rmsnorm_split_kernel(const float* __restrict__ x,
                                     const float* __restrict__ w,
                                     __nv_bfloat16* __restrict__ oh,
                                     __nv_bfloat16* __restrict__ ol) {
    const int t   = blockIdx.x;
    const int tid = threadIdx.x;
    const float4 v = reinterpret_cast<const float4*>(x + t * DMODEL)[tid];
    float s = v.x * v.x + v.y * v.y + v.z * v.z + v.w * v.w;
    #pragma unroll
    for (int o = 16; o; o >>= 1) s += __shfl_xor_sync(0xffffffffu, s, o);
    __shared__ float red[8];
    __shared__ float sscale;
    if ((tid & 31) == 0) red[tid >> 5] = s;
    __syncthreads();
    if (tid == 0) {
        float tot = 0.f;
        #pragma unroll
        for (int i = 0; i < 8; ++i) tot += red[i];
        sscale = rsqrtf(tot * (1.0f / DMODEL) + 1e-5f);
    }
    __syncthreads();
    const float sc = sscale;
    const float4 wv = reinterpret_cast<const float4*>(w)[tid];
    const int base = t * DMODEL + tid * 4;
    split2(&oh[base],     &ol[base],     v.x * sc * wv.x, v.y * sc * wv.y);
    split2(&oh[base + 2], &ol[base + 2], v.z * sc * wv.z, v.w * sc * wv.w);
}

// ---------------- depthwise causal conv + SiLU (float4/thread) ----------------
__global__ void conv_silu_kernel(const float* __restrict__ xr,
                                 const float* __restrict__ cw,
                                 const float* __restrict__ cb,
                                 float* __restrict__ xs,
                                 __nv_bfloat16* __restrict__ oh,
                                 __nv_bfloat16* __restrict__ ol) {
    const int idx = (blockIdx.x * blockDim.x + threadIdx.x) * 4;
    const int d   = idx & (DINNER - 1);
    const int tok = idx >> 11;
    const int l   = tok & (SEQ - 1);
    const float4* cw4 = reinterpret_cast<const float4*>(cw);
    const float4 w0 = cw4[d];
    const float4 w1 = cw4[d + 1];
    const float4 w2 = cw4[d + 2];
    const float4 w3 = cw4[d + 3];
    float4 a = reinterpret_cast<const float4*>(cb)[d >> 2];
    #pragma unroll
    for (int j = 0; j < 4; ++j) {
        const int ls = l - 3 + j;
        if (ls >= 0) {
            const float4 xv = *reinterpret_cast<const float4*>(
                &xr[(tok + j - 3) * (2 * DINNER) + d]);
            const float t0 = (j == 0) ? w0.x : (j == 1) ? w0.y : (j == 2) ? w0.z : w0.w;
            const float t1 = (j == 0) ? w1.x : (j == 1) ? w1.y : (j == 2) ? w1.z : w1.w;
            const float t2 = (j == 0) ? w2.x : (j == 1) ? w2.y : (j == 2) ? w2.z : w2.w;
            const float t3 = (j == 0) ? w3.x : (j == 1) ? w3.y : (j == 2) ? w3.z : w3.w;
            a.x = fmaf(t0, xv.x, a.x);
            a.y = fmaf(t1, xv.y, a.y);
            a.z = fmaf(t2, xv.z, a.z);
            a.w = fmaf(t3, xv.w, a.w);
        }
    }
    a.x = fast_silu(a.x);  a.y = fast_silu(a.y);
    a.z = fast_silu(a.z);  a.w = fast_silu(a.w);
    *reinterpret_cast<float4*>(&xs[idx]) = a;
    split2(&oh[idx],     &ol[idx],     a.x, a.y);
    split2(&oh[idx + 2], &ol[idx + 2], a.z, a.w);
}

// ---------------- merged weight split (5 segments) ----------------
// lo plane written only where the consumer GEMM is 3-term (W_x BC, W_dt).
__global__ void wsplit_all_kernel(const float* __restrict__ W1,
                                  const float* __restrict__ W2,
                                  const float* __restrict__ W3,
                                  const float* __restrict__ W4,
                                  __nv_bfloat16* __restrict__ w1h,
                                  __nv_bfloat16* __restrict__ w2h, __nv_bfloat16* __restrict__ w2l,
                                  __nv_bfloat16* __restrict__ w3h, __nv_bfloat16* __restrict__ w3l,
                                  __nv_bfloat16* __restrict__ w4h,
                                  __nv_bfloat16* __restrict__ wdh) {
    const int id = blockIdx.x;
    const int tx = threadIdx.x, ty = threadIdx.y;   // 32 x 8

    if (id >= 10496) {   // direct split (hi only) of W_x[:, :2048]
        const int rel = id - 10496;
        const int j0 = (rel & 63) * 32, k0 = (rel >> 6) * 32;
        #pragma unroll
        for (int r = 0; r < 4; ++r) {
            const int k = k0 + ty + 8 * r, j = j0 + tx;
            wdh[(size_t)k * 2048 + j] = __float2bfloat16(W2[(size_t)k * XW + j]);
        }
        return;
    }

    const float* W; __nv_bfloat16 *Th, *Tl;
    int K, N, ld, n0, k0;
    bool wlo;
    if (id < 4096) {
        W = W1; Th = w1h; Tl = nullptr; wlo = false; K = 1024; N = 4096; ld = 4096;
        n0 = (id & 127) * 32; k0 = (id >> 7) * 32;
    } else if (id < 4352) {
        const int rel = id - 4096;
        W = W2; Th = w2h; Tl = w2l; wlo = true; K = 2048; N = XW; ld = XW;
        n0 = 2048 + (rel & 3) * 32; k0 = (rel >> 2) * 32;
    } else if (id < 8448) {
        const int rel = id - 4352;
        W = W3; Th = w3h; Tl = w3l; wlo = true; K = 2048; N = 2048; ld = 2048;
        n0 = (rel & 63) * 32; k0 = (rel >> 6) * 32;
    } else {
        const int rel = id - 8448;
        W = W4; Th = w4h; Tl = nullptr; wlo = false; K = 2048; N = 1024; ld = 1024;
        n0 = (rel & 31) * 32; k0 = (rel >> 5) * 32;
    }

    __shared__ float tile[32][33];
    #pragma unroll
    for (int r = 0; r < 4; ++r) {
        const int k = k0 + ty + 8 * r, n = n0 + tx;
        tile[ty + 8 * r][tx] = (n < N) ? W[(size_t)k * ld + n] : 0.f;
    }
    __syncthreads();
    #pragma unroll
    for (int r = 0; r < 4; ++r) {
        const int nrow = n0 + ty + 8 * r, k = k0 + tx;
        const float v = tile[tx][ty + 8 * r];
        const __nv_bfloat16 hi = __float2bfloat16(v);
        Th[(size_t)nrow * K + k] = hi;
        if (wlo)
            Tl[(size_t)nrow * K + k] = __float2bfloat16(v - __bfloat162float(hi));
    }
}

// ---------------- mma.sync bf16-split GEMM (templated BM, NT terms) --------
// NT=3: D = Ah.Bh + Al.Bh + Ah.Bl    NT=2: D = Ah.Bh + Al.Bh (Bl unused)
#define TCK 32

#define ACT_NONE     0
#define ACT_RESADD   2
#define ACT_DTBC     3

template <int ACT, int SPLIT, int BM, int NT>
__global__ __launch_bounds__(256, 2)
void tcgemm_kernel(const __nv_bfloat16* __restrict__ Ah,
                   const __nv_bfloat16* __restrict__ Al,
                   const __nv_bfloat16* __restrict__ Bh,
                   const __nv_bfloat16* __restrict__ Bl,
                   float* __restrict__ D, const float* __restrict__ Res,
                   __nv_bfloat16* __restrict__ Sh, __nv_bfloat16* __restrict__ Sl,
                   int N, int K, int ldd, int ldr) {
    constexpr int TM    = BM / 32;
    constexpr int ALOFF = BM * 64;
    constexpr int BOFF  = 2 * BM * 64;
    constexpr int STAGE = BM * 128 + 16384;

    extern __shared__ unsigned char sm[];
    const uint32_t smb = smem_u32(sm);

    const int tid  = threadIdx.x;
    const int lane = tid & 31;
    const int wid  = tid >> 5;
    const int wm   = wid >> 2;
    const int wn   = wid & 3;
    const int m0   = blockIdx.y * BM;
    const int n0   = blockIdx.x * 128;

    const int lrowB = tid >> 1;
    const int gpB   = (tid & 1) * 2;
    const int swB   = (lrowB >> 1) & 3;
    const uint32_t dstB0 = BOFF + lrowB * 64 + (((gpB + 0) ^ swB) << 4);
    const uint32_t dstB1 = BOFF + lrowB * 64 + (((gpB + 1) ^ swB) << 4);
    const __nv_bfloat16* srcBh = Bh + (size_t)(n0 + lrowB) * K + gpB * 8;
    const __nv_bfloat16* srcBl = (NT == 3)
        ? Bl + (size_t)(n0 + lrowB) * K + gpB * 8 : nullptr;

    uint32_t dstA0, dstA1 = 0;
    const __nv_bfloat16 *srcAh, *srcAl;
    if constexpr (BM == 128) {
        dstA0 = lrowB * 64 + (((gpB + 0) ^ swB) << 4);
        dstA1 = lrowB * 64 + (((gpB + 1) ^ swB) << 4);
        srcAh = Ah + (size_t)(m0 + lrowB) * K + gpB * 8;
        srcAl = Al + (size_t)(m0 + lrowB) * K + gpB * 8;
    } else {
        const int lrowA = tid >> 2;
        const int gpA   = tid & 3;
        dstA0 = lrowA * 64 + ((gpA ^ ((lrowA >> 1) & 3)) << 4);
        srcAh = Ah + (size_t)(m0 + lrowA) * K + gpA * 8;
        srcAl = Al + (size_t)(m0 + lrowA) * K + gpA * 8;
    }

    const int agsel = lane >> 4;
    const int rowA  = wm * (BM / 2) + (lane & 15);
    const uint32_t offA = rowA * 64 + ((agsel ^ ((rowA >> 1) & 3)) << 4);
    const int nr    = (lane & 7) + ((lane >> 4) << 3);
    const int kgsel = (lane >> 3) & 1;
    const int rowB  = wn * 32 + nr;
    const uint32_t offB = BOFF + rowB * 64 + ((kgsel ^ ((rowB >> 1) & 3)) << 4);

    const int T = K / TCK;

    auto load_chunk = [&](int stage, int k0) {
        const uint32_t sb_ = smb + stage * STAGE;
        if constexpr (BM == 128) {
            cp_async16s(sb_ + dstA0,         srcAh + k0);
            cp_async16s(sb_ + dstA1,         srcAh + k0 + 8);
            cp_async16s(sb_ + ALOFF + dstA0, srcAl + k0);
            cp_async16s(sb_ + ALOFF + dstA1, srcAl + k0 + 8);
        } else {
            cp_async16s(sb_ + dstA0,         srcAh + k0);
            cp_async16s(sb_ + ALOFF + dstA0, srcAl + k0);
        }
        cp_async16s(sb_ + dstB0,        srcBh + k0);
        cp_async16s(sb_ + dstB1,        srcBh + k0 + 8);
        if constexpr (NT == 3) {
            cp_async16s(sb_ + 8192 + dstB0, srcBl + k0);
            cp_async16s(sb_ + 8192 + dstB1, srcBl + k0 + 8);
        }
        cp_commit();
    };

    load_chunk(0, 0);
    load_chunk(1, TCK);

    float acc[TM][4][4];
    #pragma unroll
    for (int t = 0; t < TM; ++t)
        #pragma unroll
        for (int j = 0; j < 4; ++j)
            #pragma unroll
            for (int q = 0; q < 4; ++q) acc[t][j][q] = 0.f;

    for (int i = 0; i < T; ++i) {
        asm volatile("cp.async.wait_group 1;\n" ::: "memory");
        __syncthreads();

        if (i + 2 < T) load_chunk((i + 2) % 3, (i + 2) * TCK);
        else           cp_commit();

        const uint32_t sb = smb + (i % 3) * STAGE;
        #pragma unroll
        for (int ks = 0; ks < 2; ++ks) {
            const uint32_t kx = ks * 32;
            uint32_t ah_[TM][4], al_[TM][4];
            #pragma unroll
            for (int t = 0; t < TM; ++t) {
                const uint32_t oa = (offA + t * 1024) ^ kx;
                ldsm4(ah_[t], sb + oa);
                ldsm4(al_[t], sb + ALOFF + oa);
            }
            #pragma unroll
            for (int p = 0; p < 2; ++p) {
                uint32_t bh_[4], bl_[4];
                const uint32_t ob = (offB + p * 1024) ^ kx;
                ldsm4(bh_, sb + ob);
                if constexpr (NT == 3) ldsm4(bl_, sb + ob + 8192);
                #pragma unroll
                for (int t = 0; t < TM; ++t) {
                    mma16816(acc[t][2 * p],     ah_[t], bh_);
                    mma16816(acc[t][2 * p + 1], ah_[t], bh_ + 2);
                    mma16816(acc[t][2 * p],     al_[t], bh_);
                    mma16816(acc[t][2 * p + 1], al_[t], bh_ + 2);
                    if constexpr (NT == 3) {
                        mma16816(acc[t][2 * p],     ah_[t], bl_);
                        mma16816(acc[t][2 * p + 1], ah_[t], bl_ + 2);
                    }
                }
            }
        }
    }

    // ---- epilogue
    const int g  = lane >> 2;
    const int tg = lane & 3;
    #pragma unroll
    for (int t = 0; t < TM; ++t) {
        const int row = m0 + wm * (BM / 2) + t * 16 + g;
        #pragma unroll
        for (int j = 0; j < 4; ++j) {
            const int col = n0 + wn * 32 + j * 8 + 2 * tg;
            if (col < N) {
                float c0 = acc[t][j][0], c1 = acc[t][j][1];
                float c2 = acc[t][j][2], c3 = acc[t][j][3];
                if (ACT == ACT_DTBC) {
                    if (col < DINNER) {
                        c0 = fmaxf(c0, 0.f) + __logf(1.f + __expf(-fabsf(c0)));
                        c1 = fmaxf(c1, 0.f) + __logf(1.f + __expf(-fabsf(c1)));
                        c2 = fmaxf(c2, 0.f) + __logf(1.f + __expf(-fabsf(c2)));
                        c3 = fmaxf(c3, 0.f) + __logf(1.f + __expf(-fabsf(c3)));
                        *reinterpret_cast<float2*>(&D[(size_t)row * ldd + col]) =
                            make_float2(c0, c1);
                        *reinterpret_cast<float2*>(&D[(size_t)(row + 8) * ldd + col]) =
                            make_float2(c2, c3);
                    } else {
                        float* bc = const_cast<float*>(Res);
                        *reinterpret_cast<float2*>(&bc[(size_t)row * ldr + col]) =
                            make_float2(c0, c1);
                        *reinterpret_cast<float2*>(&bc[(size_t)(row + 8) * ldr + col]) =
                            make_float2(c2, c3);
                    }
                    continue;
                }
                if (ACT == ACT_RESADD) {
                    const float2 r0 = *reinterpret_cast<const float2*>(
                        &Res[(size_t)row * ldr + col]);
                    const float2 r1 = *reinterpret_cast<const float2*>(
                        &Res[(size_t)(row + 8) * ldr + col]);
                    c0 += r0.x; c1 += r0.y; c2 += r1.x; c3 += r1.y;
                }
                const bool storef = SPLIT ? (col >= DINNER) : true;
                if (storef) {
                    *reinterpret_cast<float2*>(&D[(size_t)row * ldd + col]) =
                        make_float2(c0, c1);
                    *reinterpret_cast<float2*>(&D[(size_t)(row + 8) * ldd + col]) =
                        make_float2(c2, c3);
                }
                if (SPLIT && col < DINNER) {
                    split2(&Sh[(size_t)row * DINNER + col],
                           &Sl[(size_t)row * DINNER + col], c0, c1);
                    split2(&Sh[(size_t)(row + 8) * DINNER + col],
                           &Sl[(size_t)(row + 8) * DINNER + col], c2, c3);
                }
            }
        }
    }
}

// ---------------- chunked parallel selective scan ----------------
__global__ __launch_bounds__(256)
void scan_p1(const float* __restrict__ dt, const float* __restrict__ xs,
             const float* __restrict__ ssm, const float* __restrict__ A_log,
             float* __restrict__ P, float* __restrict__ Q) {
    __shared__ float Bsh[GSEG][DSTATE];
    const int b = blockIdx.z, s = blockIdx.y;
    const int d = blockIdx.x * 256 + threadIdx.x;
    const int tok0 = b * SEQ + s * GSEG;

    for (int v = threadIdx.x; v < GSEG * DSTATE; v += 256) {
        const int l = v >> 4, n = v & 15;
        Bsh[l][n] = ssm[(tok0 + l) * XW + DINNER + n];
    }
    __syncthreads();

    float Ac[DSTATE];
    #pragma unroll
    for (int q = 0; q < 4; ++q) {
        const float4 v = reinterpret_cast<const float4*>(&A_log[d * DSTATE])[q];
        Ac[4 * q + 0] = -__expf(v.x);  Ac[4 * q + 1] = -__expf(v.y);
        Ac[4 * q + 2] = -__expf(v.z);  Ac[4 * q + 3] = -__expf(v.w);
    }

    float h[DSTATE];
    #pragma unroll
    for (int n = 0; n < DSTATE; ++n) h[n] = 0.f;
    float sdt = 0.f;

    for (int l = 0; l < GSEG; ++l) {
        const float dtv = dt[(tok0 + l) * DINNER + d];
        const float xv  = xs[(tok0 + l) * DINNER + d];
        sdt += dtv;
        const float dtx = dtv * xv;
        #pragma unroll
        for (int n = 0; n < DSTATE; ++n)
            h[n] = fmaf(__expf(Ac[n] * dtv), h[n], dtx * Bsh[l][n]);
    }

    const int basei = ((b * NSEG + s) * DSTATE) * DINNER + d;
    #pragma unroll
    for (int n = 0; n < DSTATE; ++n) {
        P[basei + n * DINNER] = __expf(Ac[n] * sdt);
        Q[basei + n * DINNER] = h[n];
    }
}

__global__ void scan_combine(const float* __restrict__ P,
                             const float* __restrict__ Q,
                             float* __restrict__ H) {
    const int t = blockIdx.x * 256 + threadIdx.x;
    const int d = t & (DINNER - 1);
    const int n = (t >> 11) & 15;
    const int b = t >> 15;
    float h = 0.f;
    for (int s = 0; s < NSEG; ++s) {
        const int off = ((b * NSEG + s) * DSTATE + n) * DINNER + d;
        H[off] = h;
        h = fmaf(P[off], h, Q[off]);
    }
}

__global__ __launch_bounds__(256)
void scan_p2(const float* __restrict__ dt, const float* __restrict__ xs,
             const float* __restrict__ ssm, const float* __restrict__ xr,
             const float* __restrict__ A_log, const float* __restrict__ H,
             __nv_bfloat16* __restrict__ yh, __nv_bfloat16* __restrict__ yl) {
    __shared__ float Bsh[GSEG][DSTATE];
    __shared__ float Csh[GSEG][DSTATE];
    const int b = blockIdx.z, s = blockIdx.y;
    const int d = blockIdx.x * 256 + threadIdx.x;
    const int tok0 = b * SEQ + s * GSEG;

    for (int v = threadIdx.x; v < GSEG * DSTATE * 2; v += 256) {
        const int l = v >> 5, j = v & 31;
        const float val = ssm[(tok0 + l) * XW + DINNER + j];
        if (j < DSTATE) Bsh[l][j] = val;
        else            Csh[l][j - DSTATE] = val;
    }
    __syncthreads();

    float Ac[DSTATE];
    #pragma unroll
    for (int q = 0; q < 4; ++q) {
        const float4 v = reinterpret_cast<const float4*>(&A_log[d * DSTATE])[q];
        Ac[4 * q + 0] = -__expf(v.x);  Ac[4 * q + 1] = -__expf(v.y);
        Ac[4 * q + 2] = -__expf(v.z);  Ac[4 * q + 3] = -__expf(v.w);
    }

    const int basei = ((b * NSEG + s) * DSTATE) * DINNER + d;
    float h[DSTATE];
    #pragma unroll
    for (int n = 0; n < DSTATE; ++n) h[n] = H[basei + n * DINNER];

    for (int l = 0; l < GSEG; ++l) {
        const float dtv = dt[(tok0 + l) * DINNER + d];
        const float xv  = xs[(tok0 + l) * DINNER + d];
        const float dtx = dtv * xv;
        float y = 0.f;
        #pragma unroll
        for (int n = 0; n < DSTATE; ++n) {
            h[n] = fmaf(__expf(Ac[n] * dtv), h[n], dtx * Bsh[l][n]);
            y = fmaf(h[n], Csh[l][n], y);
        }
        const float r = xr[(tok0 + l) * (2 * DINNER) + DINNER + d];
        const float v = y * fast_silu(r);
        const __nv_bfloat16 hi = __float2bfloat16(v);
        yh[(tok0 + l) * DINNER + d] = hi;
        yl[(tok0 + l) * DINNER + d] = __float2bfloat16(v - __bfloat162float(hi));
    }
}

// ---------------- launch ----------------
extern "C" void kernel_launch(void* const* d_in, const int* in_sizes, int n_in,
                              void* d_out, int out_size) {
    const float* x      = (const float*)d_in[0];
    const float* rms_w  = (const float*)d_in[1];
    const float* W_in   = (const float*)d_in[2];
    const float* conv_w = (const float*)d_in[3];
    const float* conv_b = (const float*)d_in[4];
    const float* W_x    = (const float*)d_in[5];
    const float* W_dt   = (const float*)d_in[6];
    const float* A_log  = (const float*)d_in[7];
    const float* W_out  = (const float*)d_in[8];
    float* out = (float*)d_out;

    float *xr, *xs, *ssm, *dtb, *P, *Q, *H;
    __nv_bfloat16 *ah0, *al0, *ah1, *al1;
    __nv_bfloat16 *w1h, *w2h, *w2l, *w3h, *w3l, *w4h, *wdh;
    cudaGetSymbolAddress((void**)&xr,  g_xr);
    cudaGetSymbolAddress((void**)&xs,  g_xs);
    cudaGetSymbolAddress((void**)&ssm, g_ssm);
    cudaGetSymbolAddress((void**)&dtb, g_dt);
    cudaGetSymbolAddress((void**)&P,   g_P);
    cudaGetSymbolAddress((void**)&Q,   g_Q);
    cudaGetSymbolAddress((void**)&H,   g_H);
    cudaGetSymbolAddress((void**)&ah0, g_ah0);  cudaGetSymbolAddress((void**)&al0, g_al0);
    cudaGetSymbolAddress((void**)&ah1, g_ah1);  cudaGetSymbolAddress((void**)&al1, g_al1);
    cudaGetSymbolAddress((void**)&w1h, g_w1h);
    cudaGetSymbolAddress((void**)&w2h, g_w2h);  cudaGetSymbolAddress((void**)&w2l, g_w2l);
    cudaGetSymbolAddress((void**)&w3h, g_w3h);  cudaGetSymbolAddress((void**)&w3l, g_w3l);
    cudaGetSymbolAddress((void**)&w4h, g_w4h);
    cudaGetSymbolAddress((void**)&wdh, g_wxd_h);

    constexpr int SM128 = 3 * (128 * 128 + 16384);   // 98304
    constexpr int SM64  = 3 * (64 * 128 + 16384);    // 73728

    static cudaStream_t s2 = nullptr;
    static cudaEvent_t evRoot = nullptr, evW = nullptr, evJoin = nullptr;
    if (!s2) {
        cudaFuncSetAttribute(tcgemm_kernel<ACT_NONE, 0, 128, 2>,
            cudaFuncAttributeMaxDynamicSharedMemorySize, SM128);
        cudaFuncSetAttribute(tcgemm_kernel<ACT_NONE, 1, 128, 2>,
            cudaFuncAttributeMaxDynamicSharedMemorySize, SM128);
        cudaFuncSetAttribute(tcgemm_kernel<ACT_DTBC, 0, 128, 3>,
            cudaFuncAttributeMaxDynamicSharedMemorySize, SM128);
        cudaFuncSetAttribute(tcgemm_kernel<ACT_RESADD, 0, 64, 2>,
            cudaFuncAttributeMaxDynamicSharedMemorySize, SM64);
        cudaStreamCreateWithFlags(&s2, cudaStreamNonBlocking);
        cudaEventCreateWithFlags(&evRoot, cudaEventDisableTiming);
        cudaEventCreateWithFlags(&evW,    cudaEventDisableTiming);
        cudaEventCreateWithFlags(&evJoin, cudaEventDisableTiming);
    }

    // ---- s2: weight split then Wc weight GEMM (2-term)
    cudaEventRecord(evRoot, 0);
    cudaStreamWaitEvent(s2, evRoot, 0);
    wsplit_all_kernel<<<14592, dim3(32, 8), 0, s2>>>(W_in, W_x, W_dt, W_out,
        w1h, w2h, w2l, w3h, w3l, w4h, wdh);
    cudaEventRecord(evW, s2);
    // Wc^T = (W_dt^T hi/lo as A) @ (W_x hi as B); split epilogue -> w2 rows 0..2047
    tcgemm_kernel<ACT_NONE, 1, 128, 2><<<dim3(16, 16), 256, SM128, s2>>>(
        w3h, w3l, wdh, nullptr, dtb /*scratch*/, nullptr, w2h, w2l,
        2048, 2048, 2048, 0);
    cudaEventRecord(evJoin, s2);

    // ---- s0 main chain, concurrent with s2
    rmsnorm_split_kernel<<<NTOK, 256>>>(x, rms_w, ah0, al0);

    // GEMM1 (full, 2-term): xr = xn @ W_in   [2048,4096], K=1024
    cudaStreamWaitEvent(0, evW, 0);
    tcgemm_kernel<ACT_NONE, 0, 128, 2><<<dim3(32, 16), 256, SM128>>>(
        ah0, al0, w1h, nullptr, xr, nullptr, nullptr, nullptr, 4096, 1024, 4096, 0);

    // conv + silu -> xs fp32 + split buf1
    conv_silu_kernel<<<(NTOK * DINNER / 4) / 256, 256>>>(xr, conv_w, conv_b,
                                                         xs, ah1, al1);

    // fused GEMM2' (3-term): [dt | B | C] = xs @ [Wc | W_x_BC]
    cudaStreamWaitEvent(0, evJoin, 0);
    tcgemm_kernel<ACT_DTBC, 0, 128, 3><<<dim3(17, 16), 256, SM128>>>(
        ah1, al1, w2h, w2l, dtb, ssm, nullptr, nullptr,
        XW, 2048, DINNER, XW);

    // scan
    scan_p1<<<dim3(DINNER / 256, NSEG, BATCH), 256>>>(dtb, xs, ssm, A_log, P, Q);
    scan_combine<<<(BATCH * DSTATE * DINNER) / 256, 256>>>(P, Q, H);
    scan_p2<<<dim3(DINNER / 256, NSEG, BATCH), 256>>>(dtb, xs, ssm, xr, A_log, H,
                                                      ah1, al1);

    // GEMM4 (2-term): out = x + yz @ W_out
    tcgemm_kernel<ACT_RESADD, 0, 64, 2><<<dim3(8, 32), 256, SM64>>>(
        ah1, al1, w4h, nullptr, out, x, nullptr, nullptr, 1024, 2048, 1024, 1024);
}

// round 14
// speedup vs baseline: 1.5574x; 1.2386x over previous
#include <cuda_runtime.h>
#include <cuda_bf16.h>
#include <math.h>
#include <stdint.h>

// ---------------- problem constants ----------------
#define BATCH    2
#define SEQ      1024
#define DMODEL   1024
#define DINNER   2048
#define DSTATE   16
#define NTOK     (BATCH * SEQ)          // 2048
#define XW       (DINNER + 2 * DSTATE)  // 2080
#define NSEG     32
#define GSEG     32

// ---------------- fp32 scratch ----------------
__device__ float g_xr [NTOK * 2 * DINNER];
__device__ float g_xs [NTOK * DINNER];
__device__ float g_ssm[NTOK * XW];
__device__ float g_dt [NTOK * DINNER];
__device__ float g_P  [BATCH * NSEG * DSTATE * DINNER];
__device__ float g_Q  [BATCH * NSEG * DSTATE * DINNER];
__device__ float g_H  [BATCH * NSEG * DSTATE * DINNER];

// ---------------- bf16 split buffers ----------------
__device__ __nv_bfloat16 g_ah0[NTOK * DINNER];                      // xn hi (1-term GEMM1)
__device__ __nv_bfloat16 g_ah1[NTOK * DINNER], g_al1[NTOK * DINNER];// xs hi/lo; later yz hi
__device__ __nv_bfloat16 g_w1h[4096 * 1024];                        // W_in^T hi
__device__ __nv_bfloat16 g_w2h[2176 * 2048];                        // [Wc | W_x_BC]^T hi
__device__ __nv_bfloat16 g_w3h[2048 * 2048], g_w3l[2048 * 2048];   // W_dt^T hi/lo (Wc 2-term)
__device__ __nv_bfloat16 g_w4h[1024 * 2048];                        // W_out^T hi
__device__ __nv_bfloat16 g_wxd_h[2048 * 2048];                      // W_x[:, :2048] hi

// ---------------- helpers ----------------
__device__ __forceinline__ uint32_t smem_u32(const void* p) {
    uint32_t a;
    asm("{ .reg .u64 t; cvta.to.shared.u64 t, %1; cvt.u32.u64 %0, t; }"
        : "=r"(a) : "l"(p));
    return a;
}
__device__ __forceinline__ void cp_async16s(uint32_t saddr, const void* gptr) {
    asm volatile("cp.async.cg.shared.global [%0], [%1], 16;\n"
                 :: "r"(saddr), "l"(gptr));
}
__device__ __forceinline__ void cp_commit() {
    asm volatile("cp.async.commit_group;\n");
}
__device__ __forceinline__ void ldsm4(uint32_t* r, uint32_t a) {
    asm volatile("ldmatrix.sync.aligned.m8n8.x4.shared.b16 {%0,%1,%2,%3}, [%4];"
                 : "=r"(r[0]), "=r"(r[1]), "=r"(r[2]), "=r"(r[3]) : "r"(a));
}
__device__ __forceinline__ void mma16816(float* c, const uint32_t* a,
                                         const uint32_t* b) {
    asm volatile(
        "mma.sync.aligned.m16n8k16.row.col.f32.bf16.bf16.f32 "
        "{%0,%1,%2,%3}, {%4,%5,%6,%7}, {%8,%9}, {%0,%1,%2,%3};"
        : "+f"(c[0]), "+f"(c[1]), "+f"(c[2]), "+f"(c[3])
        : "r"(a[0]), "r"(a[1]), "r"(a[2]), "r"(a[3]), "r"(b[0]), "r"(b[1]));
}
__device__ __forceinline__ void split2(__nv_bfloat16* h, __nv_bfloat16* l,
                                       float v0, float v1) {
    const __nv_bfloat16 h0 = __float2bfloat16(v0);
    const __nv_bfloat16 h1 = __float2bfloat16(v1);
    __nv_bfloat162 hh; hh.x = h0; hh.y = h1;
    __nv_bfloat162 ll;
    ll.x = __float2bfloat16(v0 - __bfloat162float(h0));
    ll.y = __float2bfloat16(v1 - __bfloat162float(h1));
    *reinterpret_cast<__nv_bfloat162*>(h) = hh;
    *reinterpret_cast<__nv_bfloat162*>(l) = ll;
}
__device__ __forceinline__ void pack2h(__nv_bfloat16* h, float v0, float v1) {
    __nv_bfloat162 hh;
    hh.x = __float2bfloat16(v0);
    hh.y = __float2bfloat16(v1);
    *reinterpret_cast<__nv_bfloat162*>(h) = hh;
}
__device__ __forceinline__ float fast_silu(float a) {
    return __fdividef(a, 1.f + __expf(-a));
}

// ---------------- RMSNorm, bf16-hi output ----------------
__global__ void rmsnorm_hi_kernel(const float* __restrict__ x,
                                  const float* __restrict__ w,
                                  __nv_bfloat16* __restrict__ oh) {
    const int t   = blockIdx.x;
    const int tid = threadIdx.x;
    const float4 v = reinterpret_cast<const float4*>(x + t * DMODEL)[tid];
    float s = v.x * v.x + v.y * v.y + v.z * v.z + v.w * v.w;
    #pragma unroll
    for (int o = 16; o; o >>= 1) s += __shfl_xor_sync(0xffffffffu, s, o);
    __shared__ float red[8];
    __shared__ float sscale;
    if ((tid & 31) == 0) red[tid >> 5] = s;
    __syncthreads();
    if (tid == 0) {
        float tot = 0.f;
        #pragma unroll
        for (int i = 0; i < 8; ++i) tot += red[i];
        sscale = rsqrtf(tot * (1.0f / DMODEL) + 1e-5f);
    }
    __syncthreads();
    const float sc = sscale;
    const float4 wv = reinterpret_cast<const float4*>(w)[tid];
    const int base = t * DMODEL + tid * 4;
    pack2h(&oh[base],     v.x * sc * wv.x, v.y * sc * wv.y);
    pack2h(&oh[base + 2], v.z * sc * wv.z, v.w * sc * wv.w);
}

// ---------------- depthwise causal conv + SiLU (float4/thread) ----------------
__global__ void conv_silu_kernel(const float* __restrict__ xr,
                                 const float* __restrict__ cw,
                                 const float* __restrict__ cb,
                                 float* __restrict__ xs,
                                 __nv_bfloat16* __restrict__ oh,
                                 __nv_bfloat16* __restrict__ ol) {
    const int idx = (blockIdx.x * blockDim.x + threadIdx.x) * 4;
    const int d   = idx & (DINNER - 1);
    const int tok = idx >> 11;
    const int l   = tok & (SEQ - 1);
    const float4* cw4 = reinterpret_cast<const float4*>(cw);
    const float4 w0 = cw4[d];
    const float4 w1 = cw4[d + 1];
    const float4 w2 = cw4[d + 2];
    const float4 w3 = cw4[d + 3];
    float4 a = reinterpret_cast<const float4*>(cb)[d >> 2];
    #pragma unroll
    for (int j = 0; j < 4; ++j) {
        const int ls = l - 3 + j;
        if (ls >= 0) {
            const float4 xv = *reinterpret_cast<const float4*>(
                &xr[(tok + j - 3) * (2 * DINNER) + d]);
            const float t0 = (j == 0) ? w0.x : (j == 1) ? w0.y : (j == 2) ? w0.z : w0.w;
            const float t1 = (j == 0) ? w1.x : (j == 1) ? w1.y : (j == 2) ? w1.z : w1.w;
            const float t2 = (j == 0) ? w2.x : (j == 1) ? w2.y : (j == 2) ? w2.z : w2.w;
            const float t3 = (j == 0) ? w3.x : (j == 1) ? w3.y : (j == 2) ? w3.z : w3.w;
            a.x = fmaf(t0, xv.x, a.x);
            a.y = fmaf(t1, xv.y, a.y);
            a.z = fmaf(t2, xv.z, a.z);
            a.w = fmaf(t3, xv.w, a.w);
        }
    }
    a.x = fast_silu(a.x);  a.y = fast_silu(a.y);
    a.z = fast_silu(a.z);  a.w = fast_silu(a.w);
    *reinterpret_cast<float4*>(&xs[idx]) = a;
    split2(&oh[idx],     &ol[idx],     a.x, a.y);
    split2(&oh[idx + 2], &ol[idx + 2], a.z, a.w);
}

// ---------------- merged weight split (5 segments) ----------------
// lo plane written only for W_dt (Wc GEMM is 2-term on its A side).
__global__ void wsplit_all_kernel(const float* __restrict__ W1,
                                  const float* __restrict__ W2,
                                  const float* __restrict__ W3,
                                  const float* __restrict__ W4,
                                  __nv_bfloat16* __restrict__ w1h,
                                  __nv_bfloat16* __restrict__ w2h,
                                  __nv_bfloat16* __restrict__ w3h, __nv_bfloat16* __restrict__ w3l,
                                  __nv_bfloat16* __restrict__ w4h,
                                  __nv_bfloat16* __restrict__ wdh) {
    const int id = blockIdx.x;
    const int tx = threadIdx.x, ty = threadIdx.y;   // 32 x 8

    if (id >= 10496) {   // direct hi of W_x[:, :2048]
        const int rel = id - 10496;
        const int j0 = (rel & 63) * 32, k0 = (rel >> 6) * 32;
        #pragma unroll
        for (int r = 0; r < 4; ++r) {
            const int k = k0 + ty + 8 * r, j = j0 + tx;
            wdh[(size_t)k * 2048 + j] = __float2bfloat16(W2[(size_t)k * XW + j]);
        }
        return;
    }

    const float* W; __nv_bfloat16 *Th, *Tl;
    int K, N, ld, n0, k0;
    bool wlo;
    if (id < 4096) {
        W = W1; Th = w1h; Tl = nullptr; wlo = false; K = 1024; N = 4096; ld = 4096;
        n0 = (id & 127) * 32; k0 = (id >> 7) * 32;
    } else if (id < 4352) {
        const int rel = id - 4096;
        W = W2; Th = w2h; Tl = nullptr; wlo = false; K = 2048; N = XW; ld = XW;
        n0 = 2048 + (rel & 3) * 32; k0 = (rel >> 2) * 32;
    } else if (id < 8448) {
        const int rel = id - 4352;
        W = W3; Th = w3h; Tl = w3l; wlo = true; K = 2048; N = 2048; ld = 2048;
        n0 = (rel & 63) * 32; k0 = (rel >> 6) * 32;
    } else {
        const int rel = id - 8448;
        W = W4; Th = w4h; Tl = nullptr; wlo = false; K = 2048; N = 1024; ld = 1024;
        n0 = (rel & 31) * 32; k0 = (rel >> 5) * 32;
    }

    __shared__ float tile[32][33];
    #pragma unroll
    for (int r = 0; r < 4; ++r) {
        const int k = k0 + ty + 8 * r, n = n0 + tx;
        tile[ty + 8 * r][tx] = (n < N) ? W[(size_t)k * ld + n] : 0.f;
    }
    __syncthreads();
    #pragma unroll
    for (int r = 0; r < 4; ++r) {
        const int nrow = n0 + ty + 8 * r, k = k0 + tx;
        const float v = tile[tx][ty + 8 * r];
        const __nv_bfloat16 hi = __float2bfloat16(v);
        Th[(size_t)nrow * K + k] = hi;
        if (wlo)
            Tl[(size_t)nrow * K + k] = __float2bfloat16(v - __bfloat162float(hi));
    }
}

// ---------------- mma.sync bf16-split GEMM ----------------
// NT=1: D = Ah.Bh          NT=2: D = Ah.Bh + Al.Bh
// SPLIT=0: fp32 out only; SPLIT=1: +hi/lo bf16 split; SPLIT=2: +hi-only bf16
#define TCK 32

#define ACT_NONE     0
#define ACT_RESADD   2
#define ACT_DTBC     3

template <int ACT, int SPLIT, int BM, int NT>
__global__ __launch_bounds__(256, 2)
void tcgemm_kernel(const __nv_bfloat16* __restrict__ Ah,
                   const __nv_bfloat16* __restrict__ Al,
                   const __nv_bfloat16* __restrict__ Bh,
                   float* __restrict__ D, const float* __restrict__ Res,
                   __nv_bfloat16* __restrict__ Sh, __nv_bfloat16* __restrict__ Sl,
                   int N, int K, int ldd, int ldr) {
    constexpr int TM    = BM / 32;
    constexpr int ALOFF = BM * 64;
    constexpr int BOFF  = 2 * BM * 64;
    constexpr int STAGE = BM * 128 + 16384;

    extern __shared__ unsigned char sm[];
    const uint32_t smb = smem_u32(sm);

    const int tid  = threadIdx.x;
    const int lane = tid & 31;
    const int wid  = tid >> 5;
    const int wm   = wid >> 2;
    const int wn   = wid & 3;
    const int m0   = blockIdx.y * BM;
    const int n0   = blockIdx.x * 128;

    const int lrowB = tid >> 1;
    const int gpB   = (tid & 1) * 2;
    const int swB   = (lrowB >> 1) & 3;
    const uint32_t dstB0 = BOFF + lrowB * 64 + (((gpB + 0) ^ swB) << 4);
    const uint32_t dstB1 = BOFF + lrowB * 64 + (((gpB + 1) ^ swB) << 4);
    const __nv_bfloat16* srcBh = Bh + (size_t)(n0 + lrowB) * K + gpB * 8;

    uint32_t dstA0, dstA1 = 0;
    const __nv_bfloat16 *srcAh, *srcAl = nullptr;
    if constexpr (BM == 128) {
        dstA0 = lrowB * 64 + (((gpB + 0) ^ swB) << 4);
        dstA1 = lrowB * 64 + (((gpB + 1) ^ swB) << 4);
        srcAh = Ah + (size_t)(m0 + lrowB) * K + gpB * 8;
        if (NT >= 2) srcAl = Al + (size_t)(m0 + lrowB) * K + gpB * 8;
    } else {
        const int lrowA = tid >> 2;
        const int gpA   = tid & 3;
        dstA0 = lrowA * 64 + ((gpA ^ ((lrowA >> 1) & 3)) << 4);
        srcAh = Ah + (size_t)(m0 + lrowA) * K + gpA * 8;
        if (NT >= 2) srcAl = Al + (size_t)(m0 + lrowA) * K + gpA * 8;
    }

    const int agsel = lane >> 4;
    const int rowA  = wm * (BM / 2) + (lane & 15);
    const uint32_t offA = rowA * 64 + ((agsel ^ ((rowA >> 1) & 3)) << 4);
    const int nr    = (lane & 7) + ((lane >> 4) << 3);
    const int kgsel = (lane >> 3) & 1;
    const int rowB  = wn * 32 + nr;
    const uint32_t offB = BOFF + rowB * 64 + ((kgsel ^ ((rowB >> 1) & 3)) << 4);

    const int T = K / TCK;

    auto load_chunk = [&](int stage, int k0) {
        const uint32_t sb_ = smb + stage * STAGE;
        if constexpr (BM == 128) {
            cp_async16s(sb_ + dstA0, srcAh + k0);
            cp_async16s(sb_ + dstA1, srcAh + k0 + 8);
            if constexpr (NT >= 2) {
                cp_async16s(sb_ + ALOFF + dstA0, srcAl + k0);
                cp_async16s(sb_ + ALOFF + dstA1, srcAl + k0 + 8);
            }
        } else {
            cp_async16s(sb_ + dstA0, srcAh + k0);
            if constexpr (NT >= 2)
                cp_async16s(sb_ + ALOFF + dstA0, srcAl + k0);
        }
        cp_async16s(sb_ + dstB0, srcBh + k0);
        cp_async16s(sb_ + dstB1, srcBh + k0 + 8);
        cp_commit();
    };

    load_chunk(0, 0);
    load_chunk(1, TCK);

    float acc[TM][4][4];
    #pragma unroll
    for (int t = 0; t < TM; ++t)
        #pragma unroll
        for (int j = 0; j < 4; ++j)
            #pragma unroll
            for (int q = 0; q < 4; ++q) acc[t][j][q] = 0.f;

    for (int i = 0; i < T; ++i) {
        asm volatile("cp.async.wait_group 1;\n" ::: "memory");
        __syncthreads();

        if (i + 2 < T) load_chunk((i + 2) % 3, (i + 2) * TCK);
        else           cp_commit();

        const uint32_t sb = smb + (i % 3) * STAGE;
        #pragma unroll
        for (int ks = 0; ks < 2; ++ks) {
            const uint32_t kx = ks * 32;
            uint32_t ah_[TM][4], al_[TM][4];
            #pragma unroll
            for (int t = 0; t < TM; ++t) {
                const uint32_t oa = (offA + t * 1024) ^ kx;
                ldsm4(ah_[t], sb + oa);
                if constexpr (NT >= 2) ldsm4(al_[t], sb + ALOFF + oa);
            }
            #pragma unroll
            for (int p = 0; p < 2; ++p) {
                uint32_t bh_[4];
                const uint32_t ob = (offB + p * 1024) ^ kx;
                ldsm4(bh_, sb + ob);
                #pragma unroll
                for (int t = 0; t < TM; ++t) {
                    mma16816(acc[t][2 * p],     ah_[t], bh_);
                    mma16816(acc[t][2 * p + 1], ah_[t], bh_ + 2);
                    if constexpr (NT >= 2) {
                        mma16816(acc[t][2 * p],     al_[t], bh_);
                        mma16816(acc[t][2 * p + 1], al_[t], bh_ + 2);
                    }
                }
            }
        }
    }

    // ---- epilogue
    const int g  = lane >> 2;
    const int tg = lane & 3;
    #pragma unroll
    for (int t = 0; t < TM; ++t) {
        const int row = m0 + wm * (BM / 2) + t * 16 + g;
        #pragma unroll
        for (int j = 0; j < 4; ++j) {
            const int col = n0 + wn * 32 + j * 8 + 2 * tg;
            if (col < N) {
                float c0 = acc[t][j][0], c1 = acc[t][j][1];
                float c2 = acc[t][j][2], c3 = acc[t][j][3];
                if (ACT == ACT_DTBC) {
                    if (col < DINNER) {
                        c0 = fmaxf(c0, 0.f) + __logf(1.f + __expf(-fabsf(c0)));
                        c1 = fmaxf(c1, 0.f) + __logf(1.f + __expf(-fabsf(c1)));
                        c2 = fmaxf(c2, 0.f) + __logf(1.f + __expf(-fabsf(c2)));
                        c3 = fmaxf(c3, 0.f) + __logf(1.f + __expf(-fabsf(c3)));
                        *reinterpret_cast<float2*>(&D[(size_t)row * ldd + col]) =
                            make_float2(c0, c1);
                        *reinterpret_cast<float2*>(&D[(size_t)(row + 8) * ldd + col]) =
                            make_float2(c2, c3);
                    } else {
                        float* bc = const_cast<float*>(Res);
                        *reinterpret_cast<float2*>(&bc[(size_t)row * ldr + col]) =
                            make_float2(c0, c1);
                        *reinterpret_cast<float2*>(&bc[(size_t)(row + 8) * ldr + col]) =
                            make_float2(c2, c3);
                    }
                    continue;
                }
                if (ACT == ACT_RESADD) {
                    const float2 r0 = *reinterpret_cast<const float2*>(
                        &Res[(size_t)row * ldr + col]);
                    const float2 r1 = *reinterpret_cast<const float2*>(
                        &Res[(size_t)(row + 8) * ldr + col]);
                    c0 += r0.x; c1 += r0.y; c2 += r1.x; c3 += r1.y;
                }
                const bool storef = (SPLIT != 0) ? (col >= DINNER) : true;
                if (storef) {
                    *reinterpret_cast<float2*>(&D[(size_t)row * ldd + col]) =
                        make_float2(c0, c1);
                    *reinterpret_cast<float2*>(&D[(size_t)(row + 8) * ldd + col]) =
                        make_float2(c2, c3);
                }
                if (SPLIT == 1 && col < DINNER) {
                    split2(&Sh[(size_t)row * DINNER + col],
                           &Sl[(size_t)row * DINNER + col], c0, c1);
                    split2(&Sh[(size_t)(row + 8) * DINNER + col],
                           &Sl[(size_t)(row + 8) * DINNER + col], c2, c3);
                }
                if (SPLIT == 2 && col < DINNER) {
                    pack2h(&Sh[(size_t)row * DINNER + col], c0, c1);
                    pack2h(&Sh[(size_t)(row + 8) * DINNER + col], c2, c3);
                }
            }
        }
    }
}

// ---------------- chunked parallel selective scan ----------------
__global__ __launch_bounds__(256)
void scan_p1(const float* __restrict__ dt, const float* __restrict__ xs,
             const float* __restrict__ ssm, const float* __restrict__ A_log,
             float* __restrict__ P, float* __restrict__ Q) {
    __shared__ float Bsh[GSEG][DSTATE];
    const int b = blockIdx.z, s = blockIdx.y;
    const int d = blockIdx.x * 256 + threadIdx.x;
    const int tok0 = b * SEQ + s * GSEG;

    for (int v = threadIdx.x; v < GSEG * DSTATE; v += 256) {
        const int l = v >> 4, n = v & 15;
        Bsh[l][n] = ssm[(tok0 + l) * XW + DINNER + n];
    }
    __syncthreads();

    float Ac[DSTATE];
    #pragma unroll
    for (int q = 0; q < 4; ++q) {
        const float4 v = reinterpret_cast<const float4*>(&A_log[d * DSTATE])[q];
        Ac[4 * q + 0] = -__expf(v.x);  Ac[4 * q + 1] = -__expf(v.y);
        Ac[4 * q + 2] = -__expf(v.z);  Ac[4 * q + 3] = -__expf(v.w);
    }

    float h[DSTATE];
    #pragma unroll
    for (int n = 0; n < DSTATE; ++n) h[n] = 0.f;
    float sdt = 0.f;

    for (int l = 0; l < GSEG; ++l) {
        const float dtv = dt[(tok0 + l) * DINNER + d];
        const float xv  = xs[(tok0 + l) * DINNER + d];
        sdt += dtv;
        const float dtx = dtv * xv;
        #pragma unroll
        for (int n = 0; n < DSTATE; ++n)
            h[n] = fmaf(__expf(Ac[n] * dtv), h[n], dtx * Bsh[l][n]);
    }

    const int basei = ((b * NSEG + s) * DSTATE) * DINNER + d;
    #pragma unroll
    for (int n = 0; n < DSTATE; ++n) {
        P[basei + n * DINNER] = __expf(Ac[n] * sdt);
        Q[basei + n * DINNER] = h[n];
    }
}

__global__ void scan_combine(const float* __restrict__ P,
                             const float* __restrict__ Q,
                             float* __restrict__ H) {
    const int t = blockIdx.x * 256 + threadIdx.x;
    const int d = t & (DINNER - 1);
    const int n = (t >> 11) & 15;
    const int b = t >> 15;
    float h = 0.f;
    for (int s = 0; s < NSEG; ++s) {
        const int off = ((b * NSEG + s) * DSTATE + n) * DINNER + d;
        H[off] = h;
        h = fmaf(P[off], h, Q[off]);
    }
}

// pass 2 writes yz bf16-hi only (GEMM4 is 1-term)
__global__ __launch_bounds__(256)
void scan_p2(const float* __restrict__ dt, const float* __restrict__ xs,
             const float* __restrict__ ssm, const float* __restrict__ xr,
             const float* __restrict__ A_log, const float* __restrict__ H,
             __nv_bfloat16* __restrict__ yh) {
    __shared__ float Bsh[GSEG][DSTATE];
    __shared__ float Csh[GSEG][DSTATE];
    const int b = blockIdx.z, s = blockIdx.y;
    const int d = blockIdx.x * 256 + threadIdx.x;
    const int tok0 = b * SEQ + s * GSEG;

    for (int v = threadIdx.x; v < GSEG * DSTATE * 2; v += 256) {
        const int l = v >> 5, j = v & 31;
        const float val = ssm[(tok0 + l) * XW + DINNER + j];
        if (j < DSTATE) Bsh[l][j] = val;
        else            Csh[l][j - DSTATE] = val;
    }
    __syncthreads();

    float Ac[DSTATE];
    #pragma unroll
    for (int q = 0; q < 4; ++q) {
        const float4 v = reinterpret_cast<const float4*>(&A_log[d * DSTATE])[q];
        Ac[4 * q + 0] = -__expf(v.x);  Ac[4 * q + 1] = -__expf(v.y);
        Ac[4 * q + 2] = -__expf(v.z);  Ac[4 * q + 3] = -__expf(v.w);
    }

    const int basei = ((b * NSEG + s) * DSTATE) * DINNER + d;
    float h[DSTATE];
    #pragma unroll
    for (int n = 0; n < DSTATE; ++n) h[n] = H[basei + n * DINNER];

    for (int l = 0; l < GSEG; ++l) {
        const float dtv = dt[(tok0 + l) * DINNER + d];
        const float xv  = xs[(tok0 + l) * DINNER + d];
        const float dtx = dtv * xv;
        float y = 0.f;
        #pragma unroll
        for (int n = 0; n < DSTATE; ++n) {
            h[n] = fmaf(__expf(Ac[n] * dtv), h[n], dtx * Bsh[l][n]);
            y = fmaf(h[n], Csh[l][n], y);
        }
        const float r = xr[(tok0 + l) * (2 * DINNER) + DINNER + d];
        yh[(tok0 + l) * DINNER + d] = __float2bfloat16(y * fast_silu(r));
    }
}

// ---------------- launch ----------------
extern "C" void kernel_launch(void* const* d_in, const int* in_sizes, int n_in,
                              void* d_out, int out_size) {
    const float* x      = (const float*)d_in[0];
    const float* rms_w  = (const float*)d_in[1];
    const float* W_in   = (const float*)d_in[2];
    const float* conv_w = (const float*)d_in[3];
    const float* conv_b = (const float*)d_in[4];
    const float* W_x    = (const float*)d_in[5];
    const float* W_dt   = (const float*)d_in[6];
    const float* A_log  = (const float*)d_in[7];
    const float* W_out  = (const float*)d_in[8];
    float* out = (float*)d_out;

    float *xr, *xs, *ssm, *dtb, *P, *Q, *H;
    __nv_bfloat16 *ah0, *ah1, *al1;
    __nv_bfloat16 *w1h, *w2h, *w3h, *w3l, *w4h, *wdh;
    cudaGetSymbolAddress((void**)&xr,  g_xr);
    cudaGetSymbolAddress((void**)&xs,  g_xs);
    cudaGetSymbolAddress((void**)&ssm, g_ssm);
    cudaGetSymbolAddress((void**)&dtb, g_dt);
    cudaGetSymbolAddress((void**)&P,   g_P);
    cudaGetSymbolAddress((void**)&Q,   g_Q);
    cudaGetSymbolAddress((void**)&H,   g_H);
    cudaGetSymbolAddress((void**)&ah0, g_ah0);
    cudaGetSymbolAddress((void**)&ah1, g_ah1);  cudaGetSymbolAddress((void**)&al1, g_al1);
    cudaGetSymbolAddress((void**)&w1h, g_w1h);
    cudaGetSymbolAddress((void**)&w2h, g_w2h);
    cudaGetSymbolAddress((void**)&w3h, g_w3h);  cudaGetSymbolAddress((void**)&w3l, g_w3l);
    cudaGetSymbolAddress((void**)&w4h, g_w4h);
    cudaGetSymbolAddress((void**)&wdh, g_wxd_h);

    constexpr int SM128 = 3 * (128 * 128 + 16384);   // 98304
    constexpr int SM64  = 3 * (64 * 128 + 16384);    // 73728

    static cudaStream_t s2 = nullptr;
    static cudaEvent_t evRoot = nullptr, evW = nullptr, evJoin = nullptr;
    if (!s2) {
        cudaFuncSetAttribute(tcgemm_kernel<ACT_NONE, 0, 128, 1>,
            cudaFuncAttributeMaxDynamicSharedMemorySize, SM128);
        cudaFuncSetAttribute(tcgemm_kernel<ACT_NONE, 2, 128, 2>,
            cudaFuncAttributeMaxDynamicSharedMemorySize, SM128);
        cudaFuncSetAttribute(tcgemm_kernel<ACT_DTBC, 0, 128, 2>,
            cudaFuncAttributeMaxDynamicSharedMemorySize, SM128);
        cudaFuncSetAttribute(tcgemm_kernel<ACT_RESADD, 0, 64, 1>,
            cudaFuncAttributeMaxDynamicSharedMemorySize, SM64);
        cudaStreamCreateWithFlags(&s2, cudaStreamNonBlocking);
        cudaEventCreateWithFlags(&evRoot, cudaEventDisableTiming);
        cudaEventCreateWithFlags(&evW,    cudaEventDisableTiming);
        cudaEventCreateWithFlags(&evJoin, cudaEventDisableTiming);
    }

    // ---- s2: weight split, then Wc weight GEMM (2-term, hi-only split out)
    cudaEventRecord(evRoot, 0);
    cudaStreamWaitEvent(s2, evRoot, 0);
    wsplit_all_kernel<<<14592, dim3(32, 8), 0, s2>>>(W_in, W_x, W_dt, W_out,
        w1h, w2h, w3h, w3l, w4h, wdh);
    cudaEventRecord(evW, s2);
    tcgemm_kernel<ACT_NONE, 2, 128, 2><<<dim3(16, 16), 256, SM128, s2>>>(
        w3h, w3l, wdh, dtb /*scratch*/, nullptr, w2h, nullptr,
        2048, 2048, 2048, 0);
    cudaEventRecord(evJoin, s2);

    // ---- s0 main chain, concurrent with s2
    rmsnorm_hi_kernel<<<NTOK, 256>>>(x, rms_w, ah0);

    // GEMM1 (1-term): xr = xn @ W_in   [2048,4096], K=1024
    cudaStreamWaitEvent(0, evW, 0);
    tcgemm_kernel<ACT_NONE, 0, 128, 1><<<dim3(32, 16), 256, SM128>>>(
        ah0, nullptr, w1h, xr, nullptr, nullptr, nullptr, 4096, 1024, 4096, 0);

    // conv + silu -> xs fp32 + hi/lo split
    conv_silu_kernel<<<(NTOK * DINNER / 4) / 256, 256>>>(xr, conv_w, conv_b,
                                                         xs, ah1, al1);

    // fused GEMM2' (2-term): [dt | B | C] = xs @ [Wc | W_x_BC]
    cudaStreamWaitEvent(0, evJoin, 0);
    tcgemm_kernel<ACT_DTBC, 0, 128, 2><<<dim3(17, 16), 256, SM128>>>(
        ah1, al1, w2h, dtb, ssm, nullptr, nullptr,
        XW, 2048, DINNER, XW);

    // scan
    scan_p1<<<dim3(DINNER / 256, NSEG, BATCH), 256>>>(dtb, xs, ssm, A_log, P, Q);
    scan_combine<<<(BATCH * DSTATE * DINNER) / 256, 256>>>(P, Q, H);
    scan_p2<<<dim3(DINNER / 256, NSEG, BATCH), 256>>>(dtb, xs, ssm, xr, A_log, H,
                                                      ah1);

    // GEMM4 (1-term): out = x + yz @ W_out
    tcgemm_kernel<ACT_RESADD, 0, 64, 1><<<dim3(8, 32), 256, SM64>>>(
        ah1, nullptr, w4h, out, x, nullptr, nullptr, 1024, 2048, 1024, 1024);
}

// round 15
// speedup vs baseline: 1.9473x; 1.2504x over previous
#include <cuda_runtime.h>
#include <cuda_bf16.h>
#include <math.h>
#include <stdint.h>

// ---------------- problem constants ----------------
#define BATCH    2
#define SEQ      1024
#define DMODEL   1024
#define DINNER   2048
#define DSTATE   16
#define NTOK     (BATCH * SEQ)          // 2048
#define XW       (DINNER + 2 * DSTATE)  // 2080
#define NSEG     32
#define GSEG     32

// ---------------- fp32 scratch ----------------
__device__ float g_xr [NTOK * 2 * DINNER];
__device__ float g_xs [NTOK * DINNER];
__device__ float g_ssm[NTOK * XW];
__device__ float g_dt [NTOK * DINNER];
__device__ float g_P  [BATCH * NSEG * DSTATE * DINNER];
__device__ float g_Q  [BATCH * NSEG * DSTATE * DINNER];
__device__ float g_H  [BATCH * NSEG * DSTATE * DINNER];

// ---------------- bf16 buffers (all hi-plane only now) ----------------
__device__ __nv_bfloat16 g_ah0[NTOK * DINNER];      // xn hi
__device__ __nv_bfloat16 g_ah1[NTOK * DINNER];      // xs hi; later yz hi
__device__ __nv_bfloat16 g_w1h[4096 * 1024];        // W_in^T hi
__device__ __nv_bfloat16 g_w2h[2176 * 2048];        // [Wc | W_x_BC]^T hi
__device__ __nv_bfloat16 g_w3h[2048 * 2048];        // W_dt^T hi
__device__ __nv_bfloat16 g_w4h[1024 * 2048];        // W_out^T hi
__device__ __nv_bfloat16 g_wxd_h[2048 * 2048];      // W_x[:, :2048] hi

// ---------------- helpers ----------------
__device__ __forceinline__ uint32_t smem_u32(const void* p) {
    uint32_t a;
    asm("{ .reg .u64 t; cvta.to.shared.u64 t, %1; cvt.u32.u64 %0, t; }"
        : "=r"(a) : "l"(p));
    return a;
}
__device__ __forceinline__ void cp_async16s(uint32_t saddr, const void* gptr) {
    asm volatile("cp.async.cg.shared.global [%0], [%1], 16;\n"
                 :: "r"(saddr), "l"(gptr));
}
__device__ __forceinline__ void cp_commit() {
    asm volatile("cp.async.commit_group;\n");
}
__device__ __forceinline__ void ldsm4(uint32_t* r, uint32_t a) {
    asm volatile("ldmatrix.sync.aligned.m8n8.x4.shared.b16 {%0,%1,%2,%3}, [%4];"
                 : "=r"(r[0]), "=r"(r[1]), "=r"(r[2]), "=r"(r[3]) : "r"(a));
}
__device__ __forceinline__ void mma16816(float* c, const uint32_t* a,
                                         const uint32_t* b) {
    asm volatile(
        "mma.sync.aligned.m16n8k16.row.col.f32.bf16.bf16.f32 "
        "{%0,%1,%2,%3}, {%4,%5,%6,%7}, {%8,%9}, {%0,%1,%2,%3};"
        : "+f"(c[0]), "+f"(c[1]), "+f"(c[2]), "+f"(c[3])
        : "r"(a[0]), "r"(a[1]), "r"(a[2]), "r"(a[3]), "r"(b[0]), "r"(b[1]));
}
__device__ __forceinline__ void split2(__nv_bfloat16* h, __nv_bfloat16* l,
                                       float v0, float v1) {
    const __nv_bfloat16 h0 = __float2bfloat16(v0);
    const __nv_bfloat16 h1 = __float2bfloat16(v1);
    __nv_bfloat162 hh; hh.x = h0; hh.y = h1;
    __nv_bfloat162 ll;
    ll.x = __float2bfloat16(v0 - __bfloat162float(h0));
    ll.y = __float2bfloat16(v1 - __bfloat162float(h1));
    *reinterpret_cast<__nv_bfloat162*>(h) = hh;
    *reinterpret_cast<__nv_bfloat162*>(l) = ll;
}
__device__ __forceinline__ void pack2h(__nv_bfloat16* h, float v0, float v1) {
    __nv_bfloat162 hh;
    hh.x = __float2bfloat16(v0);
    hh.y = __float2bfloat16(v1);
    *reinterpret_cast<__nv_bfloat162*>(h) = hh;
}
__device__ __forceinline__ float fast_silu(float a) {
    return __fdividef(a, 1.f + __expf(-a));
}

// ---------------- RMSNorm, bf16-hi output ----------------
__global__ void rmsnorm_hi_kernel(const float* __restrict__ x,
                                  const float* __restrict__ w,
                                  __nv_bfloat16* __restrict__ oh) {
    const int t   = blockIdx.x;
    const int tid = threadIdx.x;
    const float4 v = reinterpret_cast<const float4*>(x + t * DMODEL)[tid];
    float s = v.x * v.x + v.y * v.y + v.z * v.z + v.w * v.w;
    #pragma unroll
    for (int o = 16; o; o >>= 1) s += __shfl_xor_sync(0xffffffffu, s, o);
    __shared__ float red[8];
    __shared__ float sscale;
    if ((tid & 31) == 0) red[tid >> 5] = s;
    __syncthreads();
    if (tid == 0) {
        float tot = 0.f;
        #pragma unroll
        for (int i = 0; i < 8; ++i) tot += red[i];
        sscale = rsqrtf(tot * (1.0f / DMODEL) + 1e-5f);
    }
    __syncthreads();
    const float sc = sscale;
    const float4 wv = reinterpret_cast<const float4*>(w)[tid];
    const int base = t * DMODEL + tid * 4;
    pack2h(&oh[base],     v.x * sc * wv.x, v.y * sc * wv.y);
    pack2h(&oh[base + 2], v.z * sc * wv.z, v.w * sc * wv.w);
}

// ---------------- depthwise causal conv + SiLU (float4/thread, hi out) -------
__global__ void conv_silu_kernel(const float* __restrict__ xr,
                                 const float* __restrict__ cw,
                                 const float* __restrict__ cb,
                                 float* __restrict__ xs,
                                 __nv_bfloat16* __restrict__ oh) {
    const int idx = (blockIdx.x * blockDim.x + threadIdx.x) * 4;
    const int d   = idx & (DINNER - 1);
    const int tok = idx >> 11;
    const int l   = tok & (SEQ - 1);
    const float4* cw4 = reinterpret_cast<const float4*>(cw);
    const float4 w0 = cw4[d];
    const float4 w1 = cw4[d + 1];
    const float4 w2 = cw4[d + 2];
    const float4 w3 = cw4[d + 3];
    float4 a = reinterpret_cast<const float4*>(cb)[d >> 2];
    #pragma unroll
    for (int j = 0; j < 4; ++j) {
        const int ls = l - 3 + j;
        if (ls >= 0) {
            const float4 xv = *reinterpret_cast<const float4*>(
                &xr[(tok + j - 3) * (2 * DINNER) + d]);
            const float t0 = (j == 0) ? w0.x : (j == 1) ? w0.y : (j == 2) ? w0.z : w0.w;
            const float t1 = (j == 0) ? w1.x : (j == 1) ? w1.y : (j == 2) ? w1.z : w1.w;
            const float t2 = (j == 0) ? w2.x : (j == 1) ? w2.y : (j == 2) ? w2.z : w2.w;
            const float t3 = (j == 0) ? w3.x : (j == 1) ? w3.y : (j == 2) ? w3.z : w3.w;
            a.x = fmaf(t0, xv.x, a.x);
            a.y = fmaf(t1, xv.y, a.y);
            a.z = fmaf(t2, xv.z, a.z);
            a.w = fmaf(t3, xv.w, a.w);
        }
    }
    a.x = fast_silu(a.x);  a.y = fast_silu(a.y);
    a.z = fast_silu(a.z);  a.w = fast_silu(a.w);
    *reinterpret_cast<float4*>(&xs[idx]) = a;
    pack2h(&oh[idx],     a.x, a.y);
    pack2h(&oh[idx + 2], a.z, a.w);
}

// ---------------- merged weight split (5 segments, hi-only everywhere) ------
__global__ void wsplit_all_kernel(const float* __restrict__ W1,
                                  const float* __restrict__ W2,
                                  const float* __restrict__ W3,
                                  const float* __restrict__ W4,
                                  __nv_bfloat16* __restrict__ w1h,
                                  __nv_bfloat16* __restrict__ w2h,
                                  __nv_bfloat16* __restrict__ w3h,
                                  __nv_bfloat16* __restrict__ w4h,
                                  __nv_bfloat16* __restrict__ wdh) {
    const int id = blockIdx.x;
    const int tx = threadIdx.x, ty = threadIdx.y;   // 32 x 8

    if (id >= 10496) {   // direct hi of W_x[:, :2048]
        const int rel = id - 10496;
        const int j0 = (rel & 63) * 32, k0 = (rel >> 6) * 32;
        #pragma unroll
        for (int r = 0; r < 4; ++r) {
            const int k = k0 + ty + 8 * r, j = j0 + tx;
            wdh[(size_t)k * 2048 + j] = __float2bfloat16(W2[(size_t)k * XW + j]);
        }
        return;
    }

    const float* W; __nv_bfloat16* Th;
    int K, N, ld, n0, k0;
    if (id < 4096) {
        W = W1; Th = w1h; K = 1024; N = 4096; ld = 4096;
        n0 = (id & 127) * 32; k0 = (id >> 7) * 32;
    } else if (id < 4352) {
        const int rel = id - 4096;
        W = W2; Th = w2h; K = 2048; N = XW; ld = XW;
        n0 = 2048 + (rel & 3) * 32; k0 = (rel >> 2) * 32;
    } else if (id < 8448) {
        const int rel = id - 4352;
        W = W3; Th = w3h; K = 2048; N = 2048; ld = 2048;
        n0 = (rel & 63) * 32; k0 = (rel >> 6) * 32;
    } else {
        const int rel = id - 8448;
        W = W4; Th = w4h; K = 2048; N = 1024; ld = 1024;
        n0 = (rel & 31) * 32; k0 = (rel >> 5) * 32;
    }

    __shared__ float tile[32][33];
    #pragma unroll
    for (int r = 0; r < 4; ++r) {
        const int k = k0 + ty + 8 * r, n = n0 + tx;
        tile[ty + 8 * r][tx] = (n < N) ? W[(size_t)k * ld + n] : 0.f;
    }
    __syncthreads();
    #pragma unroll
    for (int r = 0; r < 4; ++r) {
        const int nrow = n0 + ty + 8 * r, k = k0 + tx;
        Th[(size_t)nrow * K + k] = __float2bfloat16(tile[tx][ty + 8 * r]);
    }
}

// ---------------- mma.sync bf16 GEMM ----------------
// NT=1: D = Ah.Bh   NT=2: D = Ah.Bh + Al.Bh
// SPLIT=0: fp32 out; SPLIT=2: + hi-only bf16 out (cols < DINNER)
#define TCK 32

#define ACT_NONE     0
#define ACT_RESADD   2
#define ACT_DTBC     3

template <int ACT, int SPLIT, int BM, int NT>
__global__ __launch_bounds__(256, 2)
void tcgemm_kernel(const __nv_bfloat16* __restrict__ Ah,
                   const __nv_bfloat16* __restrict__ Al,
                   const __nv_bfloat16* __restrict__ Bh,
                   float* __restrict__ D, const float* __restrict__ Res,
                   __nv_bfloat16* __restrict__ Sh,
                   int N, int K, int ldd, int ldr) {
    constexpr int TM    = BM / 32;
    constexpr int ALOFF = BM * 64;
    constexpr int BOFF  = 2 * BM * 64;
    constexpr int STAGE = BM * 128 + 16384;

    extern __shared__ unsigned char sm[];
    const uint32_t smb = smem_u32(sm);

    const int tid  = threadIdx.x;
    const int lane = tid & 31;
    const int wid  = tid >> 5;
    const int wm   = wid >> 2;
    const int wn   = wid & 3;
    const int m0   = blockIdx.y * BM;
    const int n0   = blockIdx.x * 128;

    const int lrowB = tid >> 1;
    const int gpB   = (tid & 1) * 2;
    const int swB   = (lrowB >> 1) & 3;
    const uint32_t dstB0 = BOFF + lrowB * 64 + (((gpB + 0) ^ swB) << 4);
    const uint32_t dstB1 = BOFF + lrowB * 64 + (((gpB + 1) ^ swB) << 4);
    const __nv_bfloat16* srcBh = Bh + (size_t)(n0 + lrowB) * K + gpB * 8;

    uint32_t dstA0, dstA1 = 0;
    const __nv_bfloat16 *srcAh, *srcAl = nullptr;
    if constexpr (BM == 128) {
        dstA0 = lrowB * 64 + (((gpB + 0) ^ swB) << 4);
        dstA1 = lrowB * 64 + (((gpB + 1) ^ swB) << 4);
        srcAh = Ah + (size_t)(m0 + lrowB) * K + gpB * 8;
        if (NT >= 2) srcAl = Al + (size_t)(m0 + lrowB) * K + gpB * 8;
    } else {
        const int lrowA = tid >> 2;
        const int gpA   = tid & 3;
        dstA0 = lrowA * 64 + ((gpA ^ ((lrowA >> 1) & 3)) << 4);
        srcAh = Ah + (size_t)(m0 + lrowA) * K + gpA * 8;
        if (NT >= 2) srcAl = Al + (size_t)(m0 + lrowA) * K + gpA * 8;
    }

    const int agsel = lane >> 4;
    const int rowA  = wm * (BM / 2) + (lane & 15);
    const uint32_t offA = rowA * 64 + ((agsel ^ ((rowA >> 1) & 3)) << 4);
    const int nr    = (lane & 7) + ((lane >> 4) << 3);
    const int kgsel = (lane >> 3) & 1;
    const int rowB  = wn * 32 + nr;
    const uint32_t offB = BOFF + rowB * 64 + ((kgsel ^ ((rowB >> 1) & 3)) << 4);

    const int T = K / TCK;

    auto load_chunk = [&](int stage, int k0) {
        const uint32_t sb_ = smb + stage * STAGE;
        if constexpr (BM == 128) {
            cp_async16s(sb_ + dstA0, srcAh + k0);
            cp_async16s(sb_ + dstA1, srcAh + k0 + 8);
            if constexpr (NT >= 2) {
                cp_async16s(sb_ + ALOFF + dstA0, srcAl + k0);
                cp_async16s(sb_ + ALOFF + dstA1, srcAl + k0 + 8);
            }
        } else {
            cp_async16s(sb_ + dstA0, srcAh + k0);
            if constexpr (NT >= 2)
                cp_async16s(sb_ + ALOFF + dstA0, srcAl + k0);
        }
        cp_async16s(sb_ + dstB0, srcBh + k0);
        cp_async16s(sb_ + dstB1, srcBh + k0 + 8);
        cp_commit();
    };

    load_chunk(0, 0);
    load_chunk(1, TCK);

    float acc[TM][4][4];
    #pragma unroll
    for (int t = 0; t < TM; ++t)
        #pragma unroll
        for (int j = 0; j < 4; ++j)
            #pragma unroll
            for (int q = 0; q < 4; ++q) acc[t][j][q] = 0.f;

    for (int i = 0; i < T; ++i) {
        asm volatile("cp.async.wait_group 1;\n" ::: "memory");
        __syncthreads();

        if (i + 2 < T) load_chunk((i + 2) % 3, (i + 2) * TCK);
        else           cp_commit();

        const uint32_t sb = smb + (i % 3) * STAGE;
        #pragma unroll
        for (int ks = 0; ks < 2; ++ks) {
            const uint32_t kx = ks * 32;
            uint32_t ah_[TM][4], al_[TM][4];
            #pragma unroll
            for (int t = 0; t < TM; ++t) {
                const uint32_t oa = (offA + t * 1024) ^ kx;
                ldsm4(ah_[t], sb + oa);
                if constexpr (NT >= 2) ldsm4(al_[t], sb + ALOFF + oa);
            }
            #pragma unroll
            for (int p = 0; p < 2; ++p) {
                uint32_t bh_[4];
                const uint32_t ob = (offB + p * 1024) ^ kx;
                ldsm4(bh_, sb + ob);
                #pragma unroll
                for (int t = 0; t < TM; ++t) {
                    mma16816(acc[t][2 * p],     ah_[t], bh_);
                    mma16816(acc[t][2 * p + 1], ah_[t], bh_ + 2);
                    if constexpr (NT >= 2) {
                        mma16816(acc[t][2 * p],     al_[t], bh_);
                        mma16816(acc[t][2 * p + 1], al_[t], bh_ + 2);
                    }
                }
            }
        }
    }

    // ---- epilogue
    const int g  = lane >> 2;
    const int tg = lane & 3;
    #pragma unroll
    for (int t = 0; t < TM; ++t) {
        const int row = m0 + wm * (BM / 2) + t * 16 + g;
        #pragma unroll
        for (int j = 0; j < 4; ++j) {
            const int col = n0 + wn * 32 + j * 8 + 2 * tg;
            if (col < N) {
                float c0 = acc[t][j][0], c1 = acc[t][j][1];
                float c2 = acc[t][j][2], c3 = acc[t][j][3];
                if (ACT == ACT_DTBC) {
                    if (col < DINNER) {
                        c0 = fmaxf(c0, 0.f) + __logf(1.f + __expf(-fabsf(c0)));
                        c1 = fmaxf(c1, 0.f) + __logf(1.f + __expf(-fabsf(c1)));
                        c2 = fmaxf(c2, 0.f) + __logf(1.f + __expf(-fabsf(c2)));
                        c3 = fmaxf(c3, 0.f) + __logf(1.f + __expf(-fabsf(c3)));
                        *reinterpret_cast<float2*>(&D[(size_t)row * ldd + col]) =
                            make_float2(c0, c1);
                        *reinterpret_cast<float2*>(&D[(size_t)(row + 8) * ldd + col]) =
                            make_float2(c2, c3);
                    } else {
                        float* bc = const_cast<float*>(Res);
                        *reinterpret_cast<float2*>(&bc[(size_t)row * ldr + col]) =
                            make_float2(c0, c1);
                        *reinterpret_cast<float2*>(&bc[(size_t)(row + 8) * ldr + col]) =
                            make_float2(c2, c3);
                    }
                    continue;
                }
                if (ACT == ACT_RESADD) {
                    const float2 r0 = *reinterpret_cast<const float2*>(
                        &Res[(size_t)row * ldr + col]);
                    const float2 r1 = *reinterpret_cast<const float2*>(
                        &Res[(size_t)(row + 8) * ldr + col]);
                    c0 += r0.x; c1 += r0.y; c2 += r1.x; c3 += r1.y;
                }
                const bool storef = (SPLIT != 0) ? (col >= DINNER) : true;
                if (storef) {
                    *reinterpret_cast<float2*>(&D[(size_t)row * ldd + col]) =
                        make_float2(c0, c1);
                    *reinterpret_cast<float2*>(&D[(size_t)(row + 8) * ldd + col]) =
                        make_float2(c2, c3);
                }
                if (SPLIT == 2 && col < DINNER) {
                    pack2h(&Sh[(size_t)row * DINNER + col], c0, c1);
                    pack2h(&Sh[(size_t)(row + 8) * DINNER + col], c2, c3);
                }
            }
        }
    }
}

// ---------------- chunked parallel selective scan ----------------
__global__ __launch_bounds__(256)
void scan_p1(const float* __restrict__ dt, const float* __restrict__ xs,
             const float* __restrict__ ssm, const float* __restrict__ A_log,
             float* __restrict__ P, float* __restrict__ Q) {
    __shared__ float Bsh[GSEG][DSTATE];
    const int b = blockIdx.z, s = blockIdx.y;
    const int d = blockIdx.x * 256 + threadIdx.x;
    const int tok0 = b * SEQ + s * GSEG;

    for (int v = threadIdx.x; v < GSEG * DSTATE; v += 256) {
        const int l = v >> 4, n = v & 15;
        Bsh[l][n] = ssm[(tok0 + l) * XW + DINNER + n];
    }
    __syncthreads();

    float Ac[DSTATE];
    #pragma unroll
    for (int q = 0; q < 4; ++q) {
        const float4 v = reinterpret_cast<const float4*>(&A_log[d * DSTATE])[q];
        Ac[4 * q + 0] = -__expf(v.x);  Ac[4 * q + 1] = -__expf(v.y);
        Ac[4 * q + 2] = -__expf(v.z);  Ac[4 * q + 3] = -__expf(v.w);
    }

    float h[DSTATE];
    #pragma unroll
    for (int n = 0; n < DSTATE; ++n) h[n] = 0.f;
    float sdt = 0.f;

    for (int l = 0; l < GSEG; ++l) {
        const float dtv = dt[(tok0 + l) * DINNER + d];
        const float xv  = xs[(tok0 + l) * DINNER + d];
        sdt += dtv;
        const float dtx = dtv * xv;
        #pragma unroll
        for (int n = 0; n < DSTATE; ++n)
            h[n] = fmaf(__expf(Ac[n] * dtv), h[n], dtx * Bsh[l][n]);
    }

    const int basei = ((b * NSEG + s) * DSTATE) * DINNER + d;
    #pragma unroll
    for (int n = 0; n < DSTATE; ++n) {
        P[basei + n * DINNER] = __expf(Ac[n] * sdt);
        Q[basei + n * DINNER] = h[n];
    }
}

__global__ void scan_combine(const float* __restrict__ P,
                             const float* __restrict__ Q,
                             float* __restrict__ H) {
    const int t = blockIdx.x * 256 + threadIdx.x;
    const int d = t & (DINNER - 1);
    const int n = (t >> 11) & 15;
    const int b = t >> 15;
    float h = 0.f;
    for (int s = 0; s < NSEG; ++s) {
        const int off = ((b * NSEG + s) * DSTATE + n) * DINNER + d;
        H[off] = h;
        h = fmaf(P[off], h, Q[off]);
    }
}

__global__ __launch_bounds__(256)
void scan_p2(const float* __restrict__ dt, const float* __restrict__ xs,
             const float* __restrict__ ssm, const float* __restrict__ xr,
             const float* __restrict__ A_log, const float* __restrict__ H,
             __nv_bfloat16* __restrict__ yh) {
    __shared__ float Bsh[GSEG][DSTATE];
    __shared__ float Csh[GSEG][DSTATE];
    const int b = blockIdx.z, s = blockIdx.y;
    const int d = blockIdx.x * 256 + threadIdx.x;
    const int tok0 = b * SEQ + s * GSEG;

    for (int v = threadIdx.x; v < GSEG * DSTATE * 2; v += 256) {
        const int l = v >> 5, j = v & 31;
        const float val = ssm[(tok0 + l) * XW + DINNER + j];
        if (j < DSTATE) Bsh[l][j] = val;
        else            Csh[l][j - DSTATE] = val;
    }
    __syncthreads();

    float Ac[DSTATE];
    #pragma unroll
    for (int q = 0; q < 4; ++q) {
        const float4 v = reinterpret_cast<const float4*>(&A_log[d * DSTATE])[q];
        Ac[4 * q + 0] = -__expf(v.x);  Ac[4 * q + 1] = -__expf(v.y);
        Ac[4 * q + 2] = -__expf(v.z);  Ac[4 * q + 3] = -__expf(v.w);
    }

    const int basei = ((b * NSEG + s) * DSTATE) * DINNER + d;
    float h[DSTATE];
    #pragma unroll
    for (int n = 0; n < DSTATE; ++n) h[n] = H[basei + n * DINNER];

    for (int l = 0; l < GSEG; ++l) {
        const float dtv = dt[(tok0 + l) * DINNER + d];
        const float xv  = xs[(tok0 + l) * DINNER + d];
        const float dtx = dtv * xv;
        float y = 0.f;
        #pragma unroll
        for (int n = 0; n < DSTATE; ++n) {
            h[n] = fmaf(__expf(Ac[n] * dtv), h[n], dtx * Bsh[l][n]);
            y = fmaf(h[n], Csh[l][n], y);
        }
        const float r = xr[(tok0 + l) * (2 * DINNER) + DINNER + d];
        yh[(tok0 + l) * DINNER + d] = __float2bfloat16(y * fast_silu(r));
    }
}

// ---------------- launch ----------------
extern "C" void kernel_launch(void* const* d_in, const int* in_sizes, int n_in,
                              void* d_out, int out_size) {
    const float* x      = (const float*)d_in[0];
    const float* rms_w  = (const float*)d_in[1];
    const float* W_in   = (const float*)d_in[2];
    const float* conv_w = (const float*)d_in[3];
    const float* conv_b = (const float*)d_in[4];
    const float* W_x    = (const float*)d_in[5];
    const float* W_dt   = (const float*)d_in[6];
    const float* A_log  = (const float*)d_in[7];
    const float* W_out  = (const float*)d_in[8];
    float* out = (float*)d_out;

    float *xr, *xs, *ssm, *dtb, *P, *Q, *H;
    __nv_bfloat16 *ah0, *ah1;
    __nv_bfloat16 *w1h, *w2h, *w3h, *w4h, *wdh;
    cudaGetSymbolAddress((void**)&xr,  g_xr);
    cudaGetSymbolAddress((void**)&xs,  g_xs);
    cudaGetSymbolAddress((void**)&ssm, g_ssm);
    cudaGetSymbolAddress((void**)&dtb, g_dt);
    cudaGetSymbolAddress((void**)&P,   g_P);
    cudaGetSymbolAddress((void**)&Q,   g_Q);
    cudaGetSymbolAddress((void**)&H,   g_H);
    cudaGetSymbolAddress((void**)&ah0, g_ah0);
    cudaGetSymbolAddress((void**)&ah1, g_ah1);
    cudaGetSymbolAddress((void**)&w1h, g_w1h);
    cudaGetSymbolAddress((void**)&w2h, g_w2h);
    cudaGetSymbolAddress((void**)&w3h, g_w3h);
    cudaGetSymbolAddress((void**)&w4h, g_w4h);
    cudaGetSymbolAddress((void**)&wdh, g_wxd_h);

    constexpr int SM128 = 3 * (128 * 128 + 16384);   // 98304
    constexpr int SM64  = 3 * (64 * 128 + 16384);    // 73728

    static cudaStream_t s2 = nullptr;
    static cudaEvent_t evRoot = nullptr, evW = nullptr, evJoin = nullptr;
    if (!s2) {
        cudaFuncSetAttribute(tcgemm_kernel<ACT_NONE, 0, 128, 1>,
            cudaFuncAttributeMaxDynamicSharedMemorySize, SM128);
        cudaFuncSetAttribute(tcgemm_kernel<ACT_NONE, 2, 128, 1>,
            cudaFuncAttributeMaxDynamicSharedMemorySize, SM128);
        cudaFuncSetAttribute(tcgemm_kernel<ACT_DTBC, 0, 128, 1>,
            cudaFuncAttributeMaxDynamicSharedMemorySize, SM128);
        cudaFuncSetAttribute(tcgemm_kernel<ACT_RESADD, 0, 64, 1>,
            cudaFuncAttributeMaxDynamicSharedMemorySize, SM64);
        cudaStreamCreateWithFlags(&s2, cudaStreamNonBlocking);
        cudaEventCreateWithFlags(&evRoot, cudaEventDisableTiming);
        cudaEventCreateWithFlags(&evW,    cudaEventDisableTiming);
        cudaEventCreateWithFlags(&evJoin, cudaEventDisableTiming);
    }

    // ---- s2: weight split, then Wc weight GEMM (1-term, hi-only split out)
    cudaEventRecord(evRoot, 0);
    cudaStreamWaitEvent(s2, evRoot, 0);
    wsplit_all_kernel<<<14592, dim3(32, 8), 0, s2>>>(W_in, W_x, W_dt, W_out,
        w1h, w2h, w3h, w4h, wdh);
    cudaEventRecord(evW, s2);
    tcgemm_kernel<ACT_NONE, 2, 128, 1><<<dim3(16, 16), 256, SM128, s2>>>(
        w3h, nullptr, wdh, dtb /*scratch*/, nullptr, w2h,
        2048, 2048, 2048, 0);
    cudaEventRecord(evJoin, s2);

    // ---- s0 main chain, concurrent with s2
    rmsnorm_hi_kernel<<<NTOK, 256>>>(x, rms_w, ah0);

    // GEMM1 (1-term): xr = xn @ W_in   [2048,4096], K=1024
    cudaStreamWaitEvent(0, evW, 0);
    tcgemm_kernel<ACT_NONE, 0, 128, 1><<<dim3(32, 16), 256, SM128>>>(
        ah0, nullptr, w1h, xr, nullptr, nullptr, 4096, 1024, 4096, 0);

    // conv + silu -> xs fp32 + hi bf16
    conv_silu_kernel<<<(NTOK * DINNER / 4) / 256, 256>>>(xr, conv_w, conv_b,
                                                         xs, ah1);

    // fused GEMM2' (1-term): [dt | B | C] = xs @ [Wc | W_x_BC]
    cudaStreamWaitEvent(0, evJoin, 0);
    tcgemm_kernel<ACT_DTBC, 0, 128, 1><<<dim3(17, 16), 256, SM128>>>(
        ah1, nullptr, w2h, dtb, ssm, nullptr,
        XW, 2048, DINNER, XW);

    // scan
    scan_p1<<<dim3(DINNER / 256, NSEG, BATCH), 256>>>(dtb, xs, ssm, A_log, P, Q);
    scan_combine<<<(BATCH * DSTATE * DINNER) / 256, 256>>>(P, Q, H);
    scan_p2<<<dim3(DINNER / 256, NSEG, BATCH), 256>>>(dtb, xs, ssm, xr, A_log, H,
                                                      ah1);

    // GEMM4 (1-term): out = x + yz @ W_out
    tcgemm_kernel<ACT_RESADD, 0, 64, 1><<<dim3(8, 32), 256, SM64>>>(
        ah1, nullptr, w4h, out, x, nullptr, 1024, 2048, 1024, 1024);
}